// round 11
// baseline (speedup 1.0000x reference)
#include <cuda_runtime.h>
#include <math.h>
#include <stdint.h>

#define TNUM 2048
#define DDIM 2048
#define FDIM 512
#define ENUM 16
#define TOPK 4
#define MT   128
#define SH0  (TNUM * TOPK + ENUM * MT)   // 10240
#define HROWS (SH0 + TNUM)               // 12288
#define MAXT (HROWS / MT)                // 96

// ---------------- device scratch -------------------------------------------
__device__ float g_comb_w[TNUM * TOPK];
__device__ int   g_topk[TNUM * TOPK];
__device__ int   g_counts[ENUM];
__device__ int   g_offsets[ENUM + 1];
__device__ int   g_cursor[ENUM];
__device__ int   g_token_list[HROWS];
__device__ float g_weight_list[HROWS];
__device__ int   g_pos_of[TNUM * TOPK];
__device__ int   g_tile_seg[MAXT];
__device__ int   g_tile_r0[MAXT];
__device__ int   g_ntiles;
__device__ float g_H[(size_t)HROWS * FDIM];        // K-pair packed along F
__device__ float g_partial[(size_t)HROWS * DDIM];
// tf32-rounded, K-pair-packed copies
__device__ float g_Xp[(size_t)TNUM * DDIM];                 // [m][K packed]
__device__ float g_Wgp[(size_t)ENUM * DDIM * FDIM];         // [D/8][F][8]
__device__ float g_Wup[(size_t)ENUM * DDIM * FDIM];
__device__ float g_Wdp[(size_t)ENUM * FDIM * DDIM];         // [F/8][D][8]
__device__ float g_sWgp[(size_t)DDIM * FDIM];
__device__ float g_sWup[(size_t)DDIM * FDIM];
__device__ float g_sWdp[(size_t)FDIM * DDIM];

// inner-8 perm: packed offset o holds k%8 = perm(o); pairs (2j,2j+1) = (j, j+4)
__device__ __forceinline__ int kperm(int o) { return (o & 1) ? (o >> 1) + 4 : (o >> 1); }

// ---------------- helpers ----------------------------------------------------
__device__ __forceinline__ uint32_t smem_u32(const void* p) {
    uint32_t a;
    asm("{ .reg .u64 t; cvta.to.shared.u64 t, %1; cvt.u32.u64 %0, t; }" : "=r"(a) : "l"(p));
    return a;
}
__device__ __forceinline__ float tf32_rna(float v) {
    float o;
    asm("cvt.rna.tf32.f32 %0, %1;" : "=f"(o) : "f"(v));
    return o;
}
__device__ __forceinline__ void cpa16(uint32_t dst, const void* src, bool valid) {
    int sz = valid ? 16 : 0;
    asm volatile("cp.async.cg.shared.global [%0], [%1], 16, %2;"
                 :: "r"(dst), "l"(src), "r"(sz) : "memory");
}
#define CP_COMMIT() asm volatile("cp.async.commit_group;" ::: "memory")
#define CP_WAIT(n)  asm volatile("cp.async.wait_group %0;" :: "n"(n) : "memory")

#define MMA_TF32(C, A, b0, b1)                                                  \
    asm volatile("mma.sync.aligned.m16n8k8.row.col.f32.tf32.tf32.f32 "          \
                 "{%0,%1,%2,%3}, {%4,%5,%6,%7}, {%8,%9}, {%0,%1,%2,%3};"        \
                 : "+f"((C)[0]), "+f"((C)[1]), "+f"((C)[2]), "+f"((C)[3])       \
                 : "r"((A)[0]), "r"((A)[1]), "r"((A)[2]), "r"((A)[3]),          \
                   "r"(b0), "r"(b1))

__device__ __forceinline__ uint32_t fbits(float v) { return __float_as_uint(v); }
__device__ __forceinline__ float silu_mul(float g, float u) {
    return g / (1.f + expf(-g)) * u;
}

// ---------------- pack kernels (tf32-round + K-pair permute) -----------------
// B operand: W[K][N] row-major -> Wp[K/8][N][8] (inner 8 = perm'd k%8)
__global__ void k_pack_w(const float* __restrict__ W, float* __restrict__ Wp,
                         int K, int N) {
    __shared__ float sm[32][65];
    int z = blockIdx.z;
    W  += (size_t)z * K * N;
    Wp += (size_t)z * K * N;
    int n0 = blockIdx.x * 64, k0 = blockIdx.y * 32;
    int tid = threadIdx.x;
#pragma unroll
    for (int p = 0; p < 8; p++) {
        int idx = tid + p * 256;
        int k = idx >> 6, n = idx & 63;
        sm[k][n] = W[(size_t)(k0 + k) * N + n0 + n];
    }
    __syncthreads();
#pragma unroll
    for (int p = 0; p < 2; p++) {
        int idx = tid + p * 256;              // 512 float4 per tile
        int o4 = idx & 1, n = (idx >> 1) & 63, kb = idx >> 7;
        float4 v;
        v.x = tf32_rna(sm[kb * 8 + kperm(o4 * 4 + 0)][n]);
        v.y = tf32_rna(sm[kb * 8 + kperm(o4 * 4 + 1)][n]);
        v.z = tf32_rna(sm[kb * 8 + kperm(o4 * 4 + 2)][n]);
        v.w = tf32_rna(sm[kb * 8 + kperm(o4 * 4 + 3)][n]);
        *reinterpret_cast<float4*>(
            Wp + ((size_t)(k0 / 8 + kb) * N + n0 + n) * 8 + o4 * 4) = v;
    }
}

// A operand: X[m][K] -> row-wise inner-8 permute (k-tiles stay contiguous)
__global__ void k_pack_x(const float* __restrict__ X, float* __restrict__ Xp, int n4) {
    int i = blockIdx.x * blockDim.x + threadIdx.x;
    if (i < n4) {
        int m = i >> 9;                        // DDIM/4 = 512 float4 per row
        int c4 = (i & 511) * 4;
        const float* src = X + (size_t)m * DDIM;
        float4 v;
        v.x = tf32_rna(src[(c4 & ~7) + kperm((c4 + 0) & 7)]);
        v.y = tf32_rna(src[(c4 & ~7) + kperm((c4 + 1) & 7)]);
        v.z = tf32_rna(src[(c4 & ~7) + kperm((c4 + 2) & 7)]);
        v.w = tf32_rna(src[(c4 & ~7) + kperm((c4 + 3) & 7)]);
        *reinterpret_cast<float4*>(Xp + (size_t)m * DDIM + c4) = v;
    }
}

// ---------------- init / router / scan / scatter -----------------------------
__global__ void k_init() {
    int i = blockIdx.x * blockDim.x + threadIdx.x;
    if (i < ENUM) g_counts[i] = 0;
    for (int j = i; j < SH0; j += gridDim.x * blockDim.x) g_token_list[j] = -1;
    for (int j = i; j < TNUM; j += gridDim.x * blockDim.x) g_token_list[SH0 + j] = j;
}

__global__ void k_router(const float* __restrict__ x,
                         const float* __restrict__ gate_w,
                         const float* __restrict__ sgw) {
    int t = blockIdx.x;
    const float* xr = x + (size_t)t * DDIM;
    float acc[17];
#pragma unroll
    for (int e = 0; e < 17; e++) acc[e] = 0.f;
    for (int d = threadIdx.x; d < DDIM; d += blockDim.x) {
        float xv = xr[d];
#pragma unroll
        for (int e = 0; e < ENUM; e++) acc[e] += xv * gate_w[e * DDIM + d];
        acc[16] += xv * sgw[d];
    }
#pragma unroll
    for (int off = 16; off; off >>= 1)
#pragma unroll
        for (int e = 0; e < 17; e++) acc[e] += __shfl_down_sync(0xffffffffu, acc[e], off);
    __shared__ float red[17][4];
    int warp = threadIdx.x >> 5, lane = threadIdx.x & 31;
    if (lane == 0)
#pragma unroll
        for (int e = 0; e < 17; e++) red[e][warp] = acc[e];
    __syncthreads();
    if (threadIdx.x == 0) {
        float v[17];
#pragma unroll
        for (int e = 0; e < 17; e++) v[e] = red[e][0] + red[e][1] + red[e][2] + red[e][3];
        float lv[16];
#pragma unroll
        for (int e = 0; e < ENUM; e++) lv[e] = v[e];
        int idx[TOPK]; float lg[TOPK];
#pragma unroll
        for (int k = 0; k < TOPK; k++) {
            int bi = 0; float bv = lv[0];
#pragma unroll
            for (int e = 1; e < ENUM; e++) if (lv[e] > bv) { bv = lv[e]; bi = e; }
            idx[k] = bi; lg[k] = bv; lv[bi] = -1e30f;
        }
        float mx = lg[0], s = 0.f, w[TOPK];
#pragma unroll
        for (int k = 0; k < TOPK; k++) { w[k] = expf(lg[k] - mx); s += w[k]; }
        float inv = 1.f / s;
#pragma unroll
        for (int k = 0; k < TOPK; k++) {
            g_topk[t * TOPK + k]   = idx[k];
            g_comb_w[t * TOPK + k] = w[k] * inv;
            atomicAdd(&g_counts[idx[k]], 1);
        }
        g_weight_list[SH0 + t] = 1.f / (1.f + expf(-v[16]));
    }
}

__global__ void k_scan() {
    if (threadIdx.x == 0 && blockIdx.x == 0) {
        int o = 0, nt = 0;
        for (int e = 0; e < ENUM; e++) {
            g_offsets[e] = o;
            g_cursor[e]  = o;
            int c = (g_counts[e] + MT - 1) & ~(MT - 1);
            for (int r = 0; r < c; r += MT) { g_tile_seg[nt] = e; g_tile_r0[nt] = o + r; nt++; }
            o += c;
        }
        g_offsets[ENUM] = o;
        for (int r = 0; r < TNUM; r += MT) { g_tile_seg[nt] = ENUM; g_tile_r0[nt] = SH0 + r; nt++; }
        g_ntiles = nt;
    }
}

__global__ void k_scatter() {
    int i = blockIdx.x * blockDim.x + threadIdx.x;
    if (i < TNUM * TOPK) {
        int e = g_topk[i];
        int pos = atomicAdd(&g_cursor[e], 1);
        g_token_list[pos]  = i / TOPK;
        g_weight_list[pos] = g_comb_w[i];
        g_pos_of[i]        = pos;
    }
}

// ---------------- upgate: H = silu(X@Wg) * (X@Wu)  (mma.sync tf32) -----------
// Block 128 x 64(F). 8 warps = 4(M) x 2(F), warp 32x32 per matrix.
// SMEM: A[128 rows][36f] (packed k, float2 loads); B [4kblk][64n][12f].
#define UA_STR 36
#define UA_BUF (128 * 144)                  // 18432 B
#define UB_BUF (4 * 64 * 48)                // 12288 B
#define U_SMEM (2 * UA_BUF + 4 * UB_BUF)    // 86016 B
#define DB_BUF (4 * 128 * 48)               // 24576 B
#define D_SMEM (2 * UA_BUF + 2 * DB_BUF)    // 86016 B

__global__ void __launch_bounds__(256, 2)
k_upgate() {
    int ti = blockIdx.x;
    if (ti >= g_ntiles) return;
    int z  = g_tile_seg[ti];
    int r0 = g_tile_r0[ti];
    int f0 = blockIdx.y * 64;

    const float* Wg = (z == ENUM) ? g_sWgp : g_Wgp + (size_t)z * DDIM * FDIM;
    const float* Wu = (z == ENUM) ? g_sWup : g_Wup + (size_t)z * DDIM * FDIM;

    extern __shared__ float smf[];
    uint32_t smb = smem_u32(smf);
    __shared__ int s_tok[MT];

    int tid = threadIdx.x, lane = tid & 31;
    int warp = tid >> 5, wm = warp & 3, wf = warp >> 2;
    int g = lane >> 2, t = lane & 3;

    if (tid < MT) s_tok[tid] = g_token_list[r0 + tid];
    __syncthreads();

    float Cg[2][4][4], Cu[2][4][4];
#pragma unroll
    for (int mt = 0; mt < 2; mt++)
#pragma unroll
        for (int nt = 0; nt < 4; nt++)
#pragma unroll
            for (int q = 0; q < 4; q++) { Cg[mt][nt][q] = 0.f; Cu[mt][nt][q] = 0.f; }

#define U_LOAD(i)                                                               \
    do {                                                                        \
        int s_ = (i) & 1;                                                       \
        uint32_t a_  = smb + s_ * UA_BUF;                                       \
        uint32_t bg_ = smb + 2 * UA_BUF + s_ * UB_BUF;                          \
        uint32_t bu_ = smb + 2 * UA_BUF + 2 * UB_BUF + s_ * UB_BUF;             \
        _Pragma("unroll")                                                       \
        for (int p = 0; p < 4; p++) {                                           \
            int idx = tid + p * 256;                                            \
            int row = idx >> 3, ch = idx & 7;                                   \
            int tok = s_tok[row];                                               \
            const float* src = g_Xp + (size_t)(tok < 0 ? 0 : tok) * DDIM + (i) * 32 + ch * 4; \
            cpa16(a_ + row * 144 + ch * 16, src, tok >= 0);                     \
        }                                                                       \
        _Pragma("unroll")                                                       \
        for (int p = 0; p < 2; p++) {                                           \
            int idx = tid + p * 256;                                            \
            int o4 = idx & 1, n = (idx >> 1) & 63, kb = idx >> 7;               \
            size_t go = ((size_t)((i) * 4 + kb) * FDIM + f0 + n) * 8 + o4 * 4;  \
            uint32_t so = (kb * 64 + n) * 48 + o4 * 16;                         \
            cpa16(bg_ + so, Wg + go, true);                                     \
            cpa16(bu_ + so, Wu + go, true);                                     \
        }                                                                       \
        CP_COMMIT();                                                            \
    } while (0)

    const int NIT = DDIM / 32;   // 64
    U_LOAD(0);
    U_LOAD(1);
    for (int i = 0; i < NIT; i++) {
        if (i + 1 < NIT) CP_WAIT(1); else CP_WAIT(0);
        __syncthreads();
        int s = i & 1;
        const float* As  = smf + (s * UA_BUF) / 4;
        const float* Bgs = smf + (2 * UA_BUF + s * UB_BUF) / 4;
        const float* Bus = smf + (2 * UA_BUF + 2 * UB_BUF + s * UB_BUF) / 4;
#pragma unroll
        for (int ks = 0; ks < 4; ks++) {
            uint32_t a[2][4];
#pragma unroll
            for (int mt = 0; mt < 2; mt++) {
                const float* ab = As + (wm * 32 + mt * 16 + g) * UA_STR + ks * 8 + 2 * t;
                float2 lo = *reinterpret_cast<const float2*>(ab);
                float2 hi = *reinterpret_cast<const float2*>(ab + 8 * UA_STR);
                a[mt][0] = fbits(lo.x); a[mt][2] = fbits(lo.y);
                a[mt][1] = fbits(hi.x); a[mt][3] = fbits(hi.y);
            }
#pragma unroll
            for (int nt = 0; nt < 4; nt++) {
                int n = wf * 32 + nt * 8 + g;
                float2 bg = *reinterpret_cast<const float2*>(Bgs + (ks * 64 + n) * 12 + 2 * t);
                MMA_TF32(Cg[0][nt], a[0], fbits(bg.x), fbits(bg.y));
                MMA_TF32(Cg[1][nt], a[1], fbits(bg.x), fbits(bg.y));
                float2 bu = *reinterpret_cast<const float2*>(Bus + (ks * 64 + n) * 12 + 2 * t);
                MMA_TF32(Cu[0][nt], a[0], fbits(bu.x), fbits(bu.y));
                MMA_TF32(Cu[1][nt], a[1], fbits(bu.x), fbits(bu.y));
            }
        }
        __syncthreads();
        if (i + 2 < NIT) U_LOAD(i + 2);
    }
#undef U_LOAD

    // epilogue: SwiGLU, tf32-round, store into K-pair-packed H layout
#pragma unroll
    for (int mt = 0; mt < 2; mt++) {
        int m0 = r0 + wm * 32 + mt * 16 + g;
#pragma unroll
        for (int nt = 0; nt < 4; nt++) {
            int fb = f0 + wf * 32 + nt * 8;       // 8-aligned block base
            int r1 = t * 2, r2 = t * 2 + 1;
            int o1 = (r1 < 4) ? 2 * r1 : 2 * (r1 - 4) + 1;
            int o2 = (r2 < 4) ? 2 * r2 : 2 * (r2 - 4) + 1;
            float* h0 = g_H + (size_t)m0 * FDIM + fb;
            float* h8 = g_H + (size_t)(m0 + 8) * FDIM + fb;
            h0[o1] = tf32_rna(silu_mul(Cg[mt][nt][0], Cu[mt][nt][0]));
            h0[o2] = tf32_rna(silu_mul(Cg[mt][nt][1], Cu[mt][nt][1]));
            h8[o1] = tf32_rna(silu_mul(Cg[mt][nt][2], Cu[mt][nt][2]));
            h8[o2] = tf32_rna(silu_mul(Cg[mt][nt][3], Cu[mt][nt][3]));
        }
    }
}

// ---------------- down: partial = w * (H @ Wd)  (mma.sync tf32) --------------
// Block 128 x 128(D). 8 warps = 4(M) x 2(N), warp 32x64.
__global__ void __launch_bounds__(256, 2)
k_down() {
    int ti = blockIdx.x;
    if (ti >= g_ntiles) return;
    int z  = g_tile_seg[ti];
    int r0 = g_tile_r0[ti];
    int n0 = blockIdx.y * 128;

    const float* Wd = (z == ENUM) ? g_sWdp : g_Wdp + (size_t)z * FDIM * DDIM;

    extern __shared__ float smf[];
    uint32_t smb = smem_u32(smf);

    int tid = threadIdx.x, lane = tid & 31;
    int warp = tid >> 5, wm = warp & 3, wn = warp >> 2;
    int g = lane >> 2, t = lane & 3;

    float C[2][8][4];
#pragma unroll
    for (int mt = 0; mt < 2; mt++)
#pragma unroll
        for (int nt = 0; nt < 8; nt++)
#pragma unroll
            for (int q = 0; q < 4; q++) C[mt][nt][q] = 0.f;

#define D_LOAD(i)                                                               \
    do {                                                                        \
        int s_ = (i) & 1;                                                       \
        uint32_t a_ = smb + s_ * UA_BUF;                                        \
        uint32_t b_ = smb + 2 * UA_BUF + s_ * DB_BUF;                           \
        _Pragma("unroll")                                                       \
        for (int p = 0; p < 4; p++) {                                           \
            int idx = tid + p * 256;                                            \
            int row = idx >> 3, ch = idx & 7;                                   \
            cpa16(a_ + row * 144 + ch * 16,                                     \
                  g_H + (size_t)(r0 + row) * FDIM + (i) * 32 + ch * 4, true);   \
        }                                                                       \
        _Pragma("unroll")                                                       \
        for (int p = 0; p < 4; p++) {                                           \
            int idx = tid + p * 256;                                            \
            int o4 = idx & 1, n = (idx >> 1) & 127, kb = idx >> 8;              \
            cpa16(b_ + (kb * 128 + n) * 48 + o4 * 16,                           \
                  Wd + ((size_t)((i) * 4 + kb) * DDIM + n0 + n) * 8 + o4 * 4, true); \
        }                                                                       \
        CP_COMMIT();                                                            \
    } while (0)

    const int NIT = FDIM / 32;   // 16
    D_LOAD(0);
    D_LOAD(1);
    for (int i = 0; i < NIT; i++) {
        if (i + 1 < NIT) CP_WAIT(1); else CP_WAIT(0);
        __syncthreads();
        int s = i & 1;
        const float* As = smf + (s * UA_BUF) / 4;
        const float* Bs = smf + (2 * UA_BUF + s * DB_BUF) / 4;
#pragma unroll
        for (int ks = 0; ks < 4; ks++) {
            uint32_t a[2][4];
#pragma unroll
            for (int mt = 0; mt < 2; mt++) {
                const float* ab = As + (wm * 32 + mt * 16 + g) * UA_STR + ks * 8 + 2 * t;
                float2 lo = *reinterpret_cast<const float2*>(ab);
                float2 hi = *reinterpret_cast<const float2*>(ab + 8 * UA_STR);
                a[mt][0] = fbits(lo.x); a[mt][2] = fbits(lo.y);
                a[mt][1] = fbits(hi.x); a[mt][3] = fbits(hi.y);
            }
#pragma unroll
            for (int nt = 0; nt < 8; nt++) {
                int n = wn * 64 + nt * 8 + g;
                float2 b = *reinterpret_cast<const float2*>(Bs + (ks * 128 + n) * 12 + 2 * t);
                MMA_TF32(C[0][nt], a[0], fbits(b.x), fbits(b.y));
                MMA_TF32(C[1][nt], a[1], fbits(b.x), fbits(b.y));
            }
        }
        __syncthreads();
        if (i + 2 < NIT) D_LOAD(i + 2);
    }
#undef D_LOAD

    // epilogue: scale by routing/shared weight, store partial rows
#pragma unroll
    for (int mt = 0; mt < 2; mt++) {
        int m0 = r0 + wm * 32 + mt * 16 + g;
        float w0 = g_weight_list[m0];
        float w1 = g_weight_list[m0 + 8];
#pragma unroll
        for (int nt = 0; nt < 8; nt++) {
            int n = n0 + wn * 64 + nt * 8 + t * 2;
            float2 v;
            v.x = w0 * C[mt][nt][0];
            v.y = w0 * C[mt][nt][1];
            *reinterpret_cast<float2*>(g_partial + (size_t)m0 * DDIM + n) = v;
            v.x = w1 * C[mt][nt][2];
            v.y = w1 * C[mt][nt][3];
            *reinterpret_cast<float2*>(g_partial + (size_t)(m0 + 8) * DDIM + n) = v;
        }
    }
}

// ---------------- combine ----------------------------------------------------
__global__ void k_combine(float* __restrict__ out) {
    int t = blockIdx.x;
    int p0 = g_pos_of[t * TOPK + 0];
    int p1 = g_pos_of[t * TOPK + 1];
    int p2 = g_pos_of[t * TOPK + 2];
    int p3 = g_pos_of[t * TOPK + 3];
    const float4* a0 = (const float4*)(g_partial + (size_t)p0 * DDIM);
    const float4* a1 = (const float4*)(g_partial + (size_t)p1 * DDIM);
    const float4* a2 = (const float4*)(g_partial + (size_t)p2 * DDIM);
    const float4* a3 = (const float4*)(g_partial + (size_t)p3 * DDIM);
    const float4* as = (const float4*)(g_partial + (size_t)(SH0 + t) * DDIM);
    float4* o = (float4*)(out + (size_t)t * DDIM);
    for (int d = threadIdx.x; d < DDIM / 4; d += blockDim.x) {
        float4 v0 = a0[d], v1 = a1[d], v2 = a2[d], v3 = a3[d], vs = as[d];
        float4 r;
        r.x = v0.x + v1.x + v2.x + v3.x + vs.x;
        r.y = v0.y + v1.y + v2.y + v3.y + vs.y;
        r.z = v0.z + v1.z + v2.z + v3.z + vs.z;
        r.w = v0.w + v1.w + v2.w + v3.w + vs.w;
        o[d] = r;
    }
}

// ---------------- launch ------------------------------------------------------
extern "C" void kernel_launch(void* const* d_in, const int* in_sizes, int n_in,
                              void* d_out, int out_size) {
    const float* x   = (const float*)d_in[0];
    const float* gw  = (const float*)d_in[1];
    const float* Wg  = (const float*)d_in[2];
    const float* Wu  = (const float*)d_in[3];
    const float* Wd  = (const float*)d_in[4];
    const float* sWg = (const float*)d_in[5];
    const float* sWu = (const float*)d_in[6];
    const float* sWd = (const float*)d_in[7];
    const float* sgw = (const float*)d_in[8];
    float* out = (float*)d_out;
    (void)in_sizes; (void)n_in; (void)out_size;

    cudaFuncSetAttribute(k_upgate, cudaFuncAttributeMaxDynamicSharedMemorySize, U_SMEM);
    cudaFuncSetAttribute(k_down,   cudaFuncAttributeMaxDynamicSharedMemorySize, D_SMEM);

    float *xp, *wgp, *wup, *wdp, *swgp, *swup, *swdp;
    cudaGetSymbolAddress((void**)&xp,   g_Xp);
    cudaGetSymbolAddress((void**)&wgp,  g_Wgp);
    cudaGetSymbolAddress((void**)&wup,  g_Wup);
    cudaGetSymbolAddress((void**)&wdp,  g_Wdp);
    cudaGetSymbolAddress((void**)&swgp, g_sWgp);
    cudaGetSymbolAddress((void**)&swup, g_sWup);
    cudaGetSymbolAddress((void**)&swdp, g_sWdp);

    const int XN4 = TNUM * DDIM / 4;
    k_pack_x<<<(XN4 + 255) / 256, 256>>>(x, xp, XN4);
    // B packs: W[K][N] -> [K/8][N][8]
    k_pack_w<<<dim3(FDIM / 64, DDIM / 32, ENUM), 256>>>(Wg,  wgp,  DDIM, FDIM);
    k_pack_w<<<dim3(FDIM / 64, DDIM / 32, ENUM), 256>>>(Wu,  wup,  DDIM, FDIM);
    k_pack_w<<<dim3(DDIM / 64, FDIM / 32, ENUM), 256>>>(Wd,  wdp,  FDIM, DDIM);
    k_pack_w<<<dim3(FDIM / 64, DDIM / 32, 1),    256>>>(sWg, swgp, DDIM, FDIM);
    k_pack_w<<<dim3(FDIM / 64, DDIM / 32, 1),    256>>>(sWu, swup, DDIM, FDIM);
    k_pack_w<<<dim3(DDIM / 64, FDIM / 32, 1),    256>>>(sWd, swdp, FDIM, DDIM);

    k_init<<<8, 256>>>();
    k_router<<<TNUM, 128>>>(x, gw, sgw);
    k_scan<<<1, 1>>>();
    k_scatter<<<(TNUM * TOPK + 255) / 256, 256>>>();

    k_upgate<<<dim3(MAXT, FDIM / 64), 256, U_SMEM>>>();
    k_down<<<dim3(MAXT, DDIM / 128), 256, D_SMEM>>>();
    k_combine<<<TNUM, 256>>>(out);
}

// round 12
// speedup vs baseline: 1.6851x; 1.6851x over previous
#include <cuda_runtime.h>
#include <cuda_fp16.h>
#include <math.h>
#include <stdint.h>

#define TNUM 2048
#define DDIM 2048
#define FDIM 512
#define ENUM 16
#define TOPK 4
#define MT   128
#define SH0  (TNUM * TOPK + ENUM * MT)   // 10240
#define HROWS (SH0 + TNUM)               // 12288
#define MAXT (HROWS / MT)                // 96

// ---------------- device scratch -------------------------------------------
__device__ float g_comb_w[TNUM * TOPK];
__device__ int   g_topk[TNUM * TOPK];
__device__ int   g_counts[ENUM];
__device__ int   g_offsets[ENUM + 1];
__device__ int   g_cursor[ENUM];
__device__ int   g_token_list[HROWS];
__device__ float g_weight_list[HROWS];
__device__ int   g_pos_of[TNUM * TOPK];
__device__ int   g_tile_seg[MAXT];
__device__ int   g_tile_r0[MAXT];
__device__ int   g_ntiles;
__device__ float g_partial[(size_t)HROWS * DDIM];
// fp16 operands
__device__ __half g_Xh[(size_t)TNUM * DDIM];                // [m][D]
__device__ __half g_Hh[(size_t)HROWS * FDIM];               // [row][F]
__device__ __half g_Wgt[(size_t)ENUM * FDIM * DDIM];        // [F][D] K-major
__device__ __half g_Wut[(size_t)ENUM * FDIM * DDIM];
__device__ __half g_Wdt[(size_t)ENUM * DDIM * FDIM];        // [D][F] K-major
__device__ __half g_sWgt[(size_t)FDIM * DDIM];
__device__ __half g_sWut[(size_t)FDIM * DDIM];
__device__ __half g_sWdt[(size_t)DDIM * FDIM];

// ---------------- helpers ----------------------------------------------------
__device__ __forceinline__ uint32_t smem_u32(const void* p) {
    uint32_t a;
    asm("{ .reg .u64 t; cvta.to.shared.u64 t, %1; cvt.u32.u64 %0, t; }" : "=r"(a) : "l"(p));
    return a;
}
__device__ __forceinline__ void cpa16(uint32_t dst, const void* src, bool valid) {
    int sz = valid ? 16 : 0;
    asm volatile("cp.async.cg.shared.global [%0], [%1], 16, %2;"
                 :: "r"(dst), "l"(src), "r"(sz) : "memory");
}
#define CP_COMMIT() asm volatile("cp.async.commit_group;" ::: "memory")
#define CP_WAIT(n)  asm volatile("cp.async.wait_group %0;" :: "n"(n) : "memory")

// m16n8k16 fp16 -> f32 accumulate
#define MMA_F16(C, A, b0, b1)                                                   \
    asm volatile("mma.sync.aligned.m16n8k16.row.col.f32.f16.f16.f32 "           \
                 "{%0,%1,%2,%3}, {%4,%5,%6,%7}, {%8,%9}, {%0,%1,%2,%3};"        \
                 : "+f"((C)[0]), "+f"((C)[1]), "+f"((C)[2]), "+f"((C)[3])       \
                 : "r"((A)[0]), "r"((A)[1]), "r"((A)[2]), "r"((A)[3]),          \
                   "r"(b0), "r"(b1))

__device__ __forceinline__ float silu_mul(float g, float u) {
    return g / (1.f + expf(-g)) * u;
}

// ---------------- prepass: f32 -> fp16 (flat) --------------------------------
__global__ void k_cvth(const float4* __restrict__ src, uint2* __restrict__ dst, int n4) {
    int i = blockIdx.x * blockDim.x + threadIdx.x;
    if (i < n4) {
        float4 v = src[i];
        __half2 h0 = __floats2half2_rn(v.x, v.y);
        __half2 h1 = __floats2half2_rn(v.z, v.w);
        uint2 o;
        o.x = *reinterpret_cast<uint32_t*>(&h0);
        o.y = *reinterpret_cast<uint32_t*>(&h1);
        dst[i] = o;
    }
}

// ---------------- prepass: transpose f32[R][C] -> fp16[C][R] -----------------
__global__ void k_trh(const float* __restrict__ src, __half* __restrict__ dst,
                      int R, int C) {
    __shared__ float sm[32][33];
    int z = blockIdx.z;
    src += (size_t)z * R * C;
    dst += (size_t)z * R * C;
    int c0 = blockIdx.x * 32, r0 = blockIdx.y * 32;
    int tx = threadIdx.x, ty = threadIdx.y;
#pragma unroll
    for (int i = ty; i < 32; i += 8)
        sm[i][tx] = src[(size_t)(r0 + i) * C + c0 + tx];
    __syncthreads();
#pragma unroll
    for (int i = ty; i < 32; i += 8)
        dst[(size_t)(c0 + i) * R + r0 + tx] = __float2half_rn(sm[tx][i]);
}

// ---------------- init / router / scan / scatter -----------------------------
__global__ void k_init() {
    int i = blockIdx.x * blockDim.x + threadIdx.x;
    if (i < ENUM) g_counts[i] = 0;
    for (int j = i; j < SH0; j += gridDim.x * blockDim.x) g_token_list[j] = -1;
    for (int j = i; j < TNUM; j += gridDim.x * blockDim.x) g_token_list[SH0 + j] = j;
}

__global__ void k_router(const float* __restrict__ x,
                         const float* __restrict__ gate_w,
                         const float* __restrict__ sgw) {
    int t = blockIdx.x;
    const float* xr = x + (size_t)t * DDIM;
    float acc[17];
#pragma unroll
    for (int e = 0; e < 17; e++) acc[e] = 0.f;
    for (int d = threadIdx.x; d < DDIM; d += blockDim.x) {
        float xv = xr[d];
#pragma unroll
        for (int e = 0; e < ENUM; e++) acc[e] += xv * gate_w[e * DDIM + d];
        acc[16] += xv * sgw[d];
    }
#pragma unroll
    for (int off = 16; off; off >>= 1)
#pragma unroll
        for (int e = 0; e < 17; e++) acc[e] += __shfl_down_sync(0xffffffffu, acc[e], off);
    __shared__ float red[17][4];
    int warp = threadIdx.x >> 5, lane = threadIdx.x & 31;
    if (lane == 0)
#pragma unroll
        for (int e = 0; e < 17; e++) red[e][warp] = acc[e];
    __syncthreads();
    if (threadIdx.x == 0) {
        float v[17];
#pragma unroll
        for (int e = 0; e < 17; e++) v[e] = red[e][0] + red[e][1] + red[e][2] + red[e][3];
        float lv[16];
#pragma unroll
        for (int e = 0; e < ENUM; e++) lv[e] = v[e];
        int idx[TOPK]; float lg[TOPK];
#pragma unroll
        for (int k = 0; k < TOPK; k++) {
            int bi = 0; float bv = lv[0];
#pragma unroll
            for (int e = 1; e < ENUM; e++) if (lv[e] > bv) { bv = lv[e]; bi = e; }
            idx[k] = bi; lg[k] = bv; lv[bi] = -1e30f;
        }
        float mx = lg[0], s = 0.f, w[TOPK];
#pragma unroll
        for (int k = 0; k < TOPK; k++) { w[k] = expf(lg[k] - mx); s += w[k]; }
        float inv = 1.f / s;
#pragma unroll
        for (int k = 0; k < TOPK; k++) {
            g_topk[t * TOPK + k]   = idx[k];
            g_comb_w[t * TOPK + k] = w[k] * inv;
            atomicAdd(&g_counts[idx[k]], 1);
        }
        g_weight_list[SH0 + t] = 1.f / (1.f + expf(-v[16]));
    }
}

__global__ void k_scan() {
    if (threadIdx.x == 0 && blockIdx.x == 0) {
        int o = 0, nt = 0;
        for (int e = 0; e < ENUM; e++) {
            g_offsets[e] = o;
            g_cursor[e]  = o;
            int c = (g_counts[e] + MT - 1) & ~(MT - 1);
            for (int r = 0; r < c; r += MT) { g_tile_seg[nt] = e; g_tile_r0[nt] = o + r; nt++; }
            o += c;
        }
        g_offsets[ENUM] = o;
        for (int r = 0; r < TNUM; r += MT) { g_tile_seg[nt] = ENUM; g_tile_r0[nt] = SH0 + r; nt++; }
        g_ntiles = nt;
    }
}

__global__ void k_scatter() {
    int i = blockIdx.x * blockDim.x + threadIdx.x;
    if (i < TNUM * TOPK) {
        int e = g_topk[i];
        int pos = atomicAdd(&g_cursor[e], 1);
        g_token_list[pos]  = i / TOPK;
        g_weight_list[pos] = g_comb_w[i];
        g_pos_of[i]        = pos;
    }
}

// ---------------- SMEM geometry ----------------------------------------------
// rows of 32 fp16 (64B) padded to 80B (20 words) -> conflict-free 20g+t banking
#define ROWB   80
#define ROWW   20
#define UA_BUF (128 * ROWB)                 // 10240 B
#define UB_BUF (64 * ROWB)                  // 5120 B
#define U_SMEM (2 * UA_BUF + 4 * UB_BUF)    // 40960 B
#define DB_BUF (128 * ROWB)                 // 10240 B
#define D_SMEM (2 * UA_BUF + 2 * DB_BUF)    // 40960 B

// ---------------- upgate: H = silu(X@Wg) * (X@Wu)  (fp16 m16n8k16) -----------
// Block 128 x 64(F). 8 warps = 4(M) x 2(F); warp 32x32 per matrix.
__global__ void __launch_bounds__(256, 2)
k_upgate() {
    int ti = blockIdx.x;
    if (ti >= g_ntiles) return;
    int z  = g_tile_seg[ti];
    int r0 = g_tile_r0[ti];
    int f0 = blockIdx.y * 64;

    const __half* Wg = (z == ENUM) ? g_sWgt : g_Wgt + (size_t)z * FDIM * DDIM;
    const __half* Wu = (z == ENUM) ? g_sWut : g_Wut + (size_t)z * FDIM * DDIM;

    extern __shared__ char smc[];
    uint32_t smb = smem_u32(smc);
    __shared__ int s_tok[MT];

    int tid = threadIdx.x, lane = tid & 31;
    int warp = tid >> 5, wm = warp & 3, wf = warp >> 2;
    int g = lane >> 2, t = lane & 3;

    if (tid < MT) s_tok[tid] = g_token_list[r0 + tid];
    __syncthreads();

    float Cg[2][4][4], Cu[2][4][4];
#pragma unroll
    for (int mt = 0; mt < 2; mt++)
#pragma unroll
        for (int nt = 0; nt < 4; nt++)
#pragma unroll
            for (int q = 0; q < 4; q++) { Cg[mt][nt][q] = 0.f; Cu[mt][nt][q] = 0.f; }

#define U_LOAD(i)                                                               \
    do {                                                                        \
        int s_ = (i) & 1;                                                       \
        uint32_t a_  = smb + s_ * UA_BUF;                                       \
        uint32_t bg_ = smb + 2 * UA_BUF + s_ * UB_BUF;                          \
        uint32_t bu_ = smb + 2 * UA_BUF + 2 * UB_BUF + s_ * UB_BUF;             \
        _Pragma("unroll")                                                       \
        for (int p = 0; p < 2; p++) {                                           \
            int idx = tid + p * 256;                                            \
            int row = idx >> 2, ch = idx & 3;                                   \
            int tok = s_tok[row];                                               \
            cpa16(a_ + row * ROWB + ch * 16,                                    \
                  g_Xh + (size_t)(tok < 0 ? 0 : tok) * DDIM + (i) * 32 + ch * 8,\
                  tok >= 0);                                                    \
        }                                                                       \
        {                                                                       \
            int row = tid >> 2, ch = tid & 3;                                   \
            cpa16(bg_ + row * ROWB + ch * 16,                                   \
                  Wg + (size_t)(f0 + row) * DDIM + (i) * 32 + ch * 8, true);    \
            cpa16(bu_ + row * ROWB + ch * 16,                                   \
                  Wu + (size_t)(f0 + row) * DDIM + (i) * 32 + ch * 8, true);    \
        }                                                                       \
        CP_COMMIT();                                                            \
    } while (0)

    const int NIT = DDIM / 32;   // 64
    U_LOAD(0);
    U_LOAD(1);
    for (int i = 0; i < NIT; i++) {
        if (i + 1 < NIT) CP_WAIT(1); else CP_WAIT(0);
        __syncthreads();
        int s = i & 1;
        const uint32_t* As32 = (const uint32_t*)(smc + s * UA_BUF);
        const uint32_t* Bg32 = (const uint32_t*)(smc + 2 * UA_BUF + s * UB_BUF);
        const uint32_t* Bu32 = (const uint32_t*)(smc + 2 * UA_BUF + 2 * UB_BUF + s * UB_BUF);
#pragma unroll
        for (int s2 = 0; s2 < 2; s2++) {
            int kw = s2 * 8 + t;
            uint32_t a[2][4];
#pragma unroll
            for (int mt = 0; mt < 2; mt++) {
                const uint32_t* ar = As32 + (wm * 32 + mt * 16 + g) * ROWW + kw;
                a[mt][0] = ar[0];
                a[mt][1] = ar[8 * ROWW];
                a[mt][2] = ar[4];
                a[mt][3] = ar[8 * ROWW + 4];
            }
#pragma unroll
            for (int nt = 0; nt < 4; nt++) {
                int n = wf * 32 + nt * 8 + g;
                const uint32_t* bp = Bg32 + n * ROWW + kw;
                uint32_t b0 = bp[0], b1 = bp[4];
                MMA_F16(Cg[0][nt], a[0], b0, b1);
                MMA_F16(Cg[1][nt], a[1], b0, b1);
                bp = Bu32 + n * ROWW + kw;
                b0 = bp[0]; b1 = bp[4];
                MMA_F16(Cu[0][nt], a[0], b0, b1);
                MMA_F16(Cu[1][nt], a[1], b0, b1);
            }
        }
        __syncthreads();
        if (i + 2 < NIT) U_LOAD(i + 2);
    }
#undef U_LOAD

    // epilogue: SwiGLU in-register, half2 store into natural H layout
#pragma unroll
    for (int mt = 0; mt < 2; mt++) {
        int m0 = r0 + wm * 32 + mt * 16 + g;
#pragma unroll
        for (int nt = 0; nt < 4; nt++) {
            int fb = f0 + wf * 32 + nt * 8 + 2 * t;
            __half2 h;
            h = __floats2half2_rn(silu_mul(Cg[mt][nt][0], Cu[mt][nt][0]),
                                  silu_mul(Cg[mt][nt][1], Cu[mt][nt][1]));
            *reinterpret_cast<__half2*>(g_Hh + (size_t)m0 * FDIM + fb) = h;
            h = __floats2half2_rn(silu_mul(Cg[mt][nt][2], Cu[mt][nt][2]),
                                  silu_mul(Cg[mt][nt][3], Cu[mt][nt][3]));
            *reinterpret_cast<__half2*>(g_Hh + (size_t)(m0 + 8) * FDIM + fb) = h;
        }
    }
}

// ---------------- down: partial = w * (H @ Wd)  (fp16 m16n8k16) --------------
// Block 128 x 128(D). 8 warps = 4(M) x 2(N); warp 32x64.
__global__ void __launch_bounds__(256, 2)
k_down() {
    int ti = blockIdx.x;
    if (ti >= g_ntiles) return;
    int z  = g_tile_seg[ti];
    int r0 = g_tile_r0[ti];
    int n0 = blockIdx.y * 128;

    const __half* Wd = (z == ENUM) ? g_sWdt : g_Wdt + (size_t)z * DDIM * FDIM;

    extern __shared__ char smc[];
    uint32_t smb = smem_u32(smc);

    int tid = threadIdx.x, lane = tid & 31;
    int warp = tid >> 5, wm = warp & 3, wn = warp >> 2;
    int g = lane >> 2, t = lane & 3;

    float C[2][8][4];
#pragma unroll
    for (int mt = 0; mt < 2; mt++)
#pragma unroll
        for (int nt = 0; nt < 8; nt++)
#pragma unroll
            for (int q = 0; q < 4; q++) C[mt][nt][q] = 0.f;

#define D_LOAD(i)                                                               \
    do {                                                                        \
        int s_ = (i) & 1;                                                       \
        uint32_t a_ = smb + s_ * UA_BUF;                                        \
        uint32_t b_ = smb + 2 * UA_BUF + s_ * DB_BUF;                           \
        _Pragma("unroll")                                                       \
        for (int p = 0; p < 2; p++) {                                           \
            int idx = tid + p * 256;                                            \
            int row = idx >> 2, ch = idx & 3;                                   \
            cpa16(a_ + row * ROWB + ch * 16,                                    \
                  g_Hh + (size_t)(r0 + row) * FDIM + (i) * 32 + ch * 8, true);  \
            cpa16(b_ + row * ROWB + ch * 16,                                    \
                  Wd + (size_t)(n0 + row) * FDIM + (i) * 32 + ch * 8, true);    \
        }                                                                       \
        CP_COMMIT();                                                            \
    } while (0)

    const int NIT = FDIM / 32;   // 16
    D_LOAD(0);
    D_LOAD(1);
    for (int i = 0; i < NIT; i++) {
        if (i + 1 < NIT) CP_WAIT(1); else CP_WAIT(0);
        __syncthreads();
        int s = i & 1;
        const uint32_t* As32 = (const uint32_t*)(smc + s * UA_BUF);
        const uint32_t* Bs32 = (const uint32_t*)(smc + 2 * UA_BUF + s * DB_BUF);
#pragma unroll
        for (int s2 = 0; s2 < 2; s2++) {
            int kw = s2 * 8 + t;
            uint32_t a[2][4];
#pragma unroll
            for (int mt = 0; mt < 2; mt++) {
                const uint32_t* ar = As32 + (wm * 32 + mt * 16 + g) * ROWW + kw;
                a[mt][0] = ar[0];
                a[mt][1] = ar[8 * ROWW];
                a[mt][2] = ar[4];
                a[mt][3] = ar[8 * ROWW + 4];
            }
#pragma unroll
            for (int nt = 0; nt < 8; nt++) {
                int n = wn * 64 + nt * 8 + g;
                const uint32_t* bp = Bs32 + n * ROWW + kw;
                uint32_t b0 = bp[0], b1 = bp[4];
                MMA_F16(C[0][nt], a[0], b0, b1);
                MMA_F16(C[1][nt], a[1], b0, b1);
            }
        }
        __syncthreads();
        if (i + 2 < NIT) D_LOAD(i + 2);
    }
#undef D_LOAD

    // epilogue: scale by routing/shared weight, store f32 partial rows
#pragma unroll
    for (int mt = 0; mt < 2; mt++) {
        int m0 = r0 + wm * 32 + mt * 16 + g;
        float w0 = g_weight_list[m0];
        float w1 = g_weight_list[m0 + 8];
#pragma unroll
        for (int nt = 0; nt < 8; nt++) {
            int n = n0 + wn * 64 + nt * 8 + t * 2;
            float2 v;
            v.x = w0 * C[mt][nt][0];
            v.y = w0 * C[mt][nt][1];
            *reinterpret_cast<float2*>(g_partial + (size_t)m0 * DDIM + n) = v;
            v.x = w1 * C[mt][nt][2];
            v.y = w1 * C[mt][nt][3];
            *reinterpret_cast<float2*>(g_partial + (size_t)(m0 + 8) * DDIM + n) = v;
        }
    }
}

// ---------------- combine ----------------------------------------------------
__global__ void k_combine(float* __restrict__ out) {
    int t = blockIdx.x;
    int p0 = g_pos_of[t * TOPK + 0];
    int p1 = g_pos_of[t * TOPK + 1];
    int p2 = g_pos_of[t * TOPK + 2];
    int p3 = g_pos_of[t * TOPK + 3];
    const float4* a0 = (const float4*)(g_partial + (size_t)p0 * DDIM);
    const float4* a1 = (const float4*)(g_partial + (size_t)p1 * DDIM);
    const float4* a2 = (const float4*)(g_partial + (size_t)p2 * DDIM);
    const float4* a3 = (const float4*)(g_partial + (size_t)p3 * DDIM);
    const float4* as = (const float4*)(g_partial + (size_t)(SH0 + t) * DDIM);
    float4* o = (float4*)(out + (size_t)t * DDIM);
    for (int d = threadIdx.x; d < DDIM / 4; d += blockDim.x) {
        float4 v0 = a0[d], v1 = a1[d], v2 = a2[d], v3 = a3[d], vs = as[d];
        float4 r;
        r.x = v0.x + v1.x + v2.x + v3.x + vs.x;
        r.y = v0.y + v1.y + v2.y + v3.y + vs.y;
        r.z = v0.z + v1.z + v2.z + v3.z + vs.z;
        r.w = v0.w + v1.w + v2.w + v3.w + vs.w;
        o[d] = r;
    }
}

// ---------------- launch ------------------------------------------------------
extern "C" void kernel_launch(void* const* d_in, const int* in_sizes, int n_in,
                              void* d_out, int out_size) {
    const float* x   = (const float*)d_in[0];
    const float* gw  = (const float*)d_in[1];
    const float* Wg  = (const float*)d_in[2];
    const float* Wu  = (const float*)d_in[3];
    const float* Wd  = (const float*)d_in[4];
    const float* sWg = (const float*)d_in[5];
    const float* sWu = (const float*)d_in[6];
    const float* sWd = (const float*)d_in[7];
    const float* sgw = (const float*)d_in[8];
    float* out = (float*)d_out;
    (void)in_sizes; (void)n_in; (void)out_size;

    __half *xh, *wgt, *wut, *wdt, *swgt, *swut, *swdt;
    cudaGetSymbolAddress((void**)&xh,   g_Xh);
    cudaGetSymbolAddress((void**)&wgt,  g_Wgt);
    cudaGetSymbolAddress((void**)&wut,  g_Wut);
    cudaGetSymbolAddress((void**)&wdt,  g_Wdt);
    cudaGetSymbolAddress((void**)&swgt, g_sWgt);
    cudaGetSymbolAddress((void**)&swut, g_sWut);
    cudaGetSymbolAddress((void**)&swdt, g_sWdt);

    // X: flat f32 -> fp16
    const int XN4 = TNUM * DDIM / 4;
    k_cvth<<<(XN4 + 255) / 256, 256>>>((const float4*)x, (uint2*)xh, XN4);
    // Weights: transpose + fp16 round. Wg/Wu [D][F] -> [F][D]; Wd [F][D] -> [D][F]
    dim3 trb(32, 8);
    k_trh<<<dim3(FDIM / 32, DDIM / 32, ENUM), trb>>>(Wg,  wgt,  DDIM, FDIM);
    k_trh<<<dim3(FDIM / 32, DDIM / 32, ENUM), trb>>>(Wu,  wut,  DDIM, FDIM);
    k_trh<<<dim3(DDIM / 32, FDIM / 32, ENUM), trb>>>(Wd,  wdt,  FDIM, DDIM);
    k_trh<<<dim3(FDIM / 32, DDIM / 32, 1),    trb>>>(sWg, swgt, DDIM, FDIM);
    k_trh<<<dim3(FDIM / 32, DDIM / 32, 1),    trb>>>(sWu, swut, DDIM, FDIM);
    k_trh<<<dim3(DDIM / 32, FDIM / 32, 1),    trb>>>(sWd, swdt, FDIM, DDIM);

    k_init<<<8, 256>>>();
    k_router<<<TNUM, 128>>>(x, gw, sgw);
    k_scan<<<1, 1>>>();
    k_scatter<<<(TNUM * TOPK + 255) / 256, 256>>>();

    k_upgate<<<dim3(MAXT, FDIM / 64), 256, U_SMEM>>>();
    k_down<<<dim3(MAXT, DDIM / 128), 256, D_SMEM>>>();
    k_combine<<<TNUM, 256>>>(out);
}

// round 13
// speedup vs baseline: 1.9387x; 1.1505x over previous
#include <cuda_runtime.h>
#include <cuda_fp16.h>
#include <math.h>
#include <stdint.h>

#define TNUM 2048
#define DDIM 2048
#define FDIM 512
#define ENUM 16
#define TOPK 4
#define MT   128
#define SH0  (TNUM * TOPK + ENUM * MT)   // 10240
#define HROWS (SH0 + TNUM)               // 12288
#define MAXT (HROWS / MT)                // 96

// ---------------- device scratch -------------------------------------------
__device__ float g_comb_w[TNUM * TOPK];
__device__ int   g_topk[TNUM * TOPK];
__device__ int   g_counts[ENUM];
__device__ int   g_offsets[ENUM + 1];
__device__ int   g_cursor[ENUM];
__device__ int   g_token_list[HROWS];
__device__ float g_weight_list[HROWS];
__device__ int   g_pos_of[TNUM * TOPK];
__device__ int   g_tile_seg[MAXT];
__device__ int   g_tile_r0[MAXT];
__device__ int   g_ntiles;
__device__ float g_partial[(size_t)HROWS * DDIM];
// fp16 operands
__device__ __half g_Xh[(size_t)TNUM * DDIM];                // [m][D]
__device__ __half g_Hh[(size_t)HROWS * FDIM];               // [row][F]
__device__ __half g_Wgt[(size_t)ENUM * FDIM * DDIM];        // [F][D] K-major
__device__ __half g_Wut[(size_t)ENUM * FDIM * DDIM];
__device__ __half g_Wdt[(size_t)ENUM * DDIM * FDIM];        // [D][F] K-major
__device__ __half g_sWgt[(size_t)FDIM * DDIM];
__device__ __half g_sWut[(size_t)FDIM * DDIM];
__device__ __half g_sWdt[(size_t)DDIM * FDIM];

// ---------------- helpers ----------------------------------------------------
__device__ __forceinline__ uint32_t smem_u32(const void* p) {
    uint32_t a;
    asm("{ .reg .u64 t; cvta.to.shared.u64 t, %1; cvt.u32.u64 %0, t; }" : "=r"(a) : "l"(p));
    return a;
}
__device__ __forceinline__ void cpa16(uint32_t dst, const void* src, bool valid) {
    int sz = valid ? 16 : 0;
    asm volatile("cp.async.cg.shared.global [%0], [%1], 16, %2;"
                 :: "r"(dst), "l"(src), "r"(sz) : "memory");
}
#define CP_COMMIT() asm volatile("cp.async.commit_group;" ::: "memory")
#define CP_WAIT(n)  asm volatile("cp.async.wait_group %0;" :: "n"(n) : "memory")

// m16n8k16 fp16 -> f32 accumulate
#define MMA_F16(C, A, b0, b1)                                                   \
    asm volatile("mma.sync.aligned.m16n8k16.row.col.f32.f16.f16.f32 "           \
                 "{%0,%1,%2,%3}, {%4,%5,%6,%7}, {%8,%9}, {%0,%1,%2,%3};"        \
                 : "+f"((C)[0]), "+f"((C)[1]), "+f"((C)[2]), "+f"((C)[3])       \
                 : "r"((A)[0]), "r"((A)[1]), "r"((A)[2]), "r"((A)[3]),          \
                   "r"(b0), "r"(b1))

__device__ __forceinline__ float silu_mul(float g, float u) {
    return g / (1.f + expf(-g)) * u;
}

// ---------------- prepass: f32 -> fp16 (flat) --------------------------------
__global__ void k_cvth(const float4* __restrict__ src, uint2* __restrict__ dst, int n4) {
    int i = blockIdx.x * blockDim.x + threadIdx.x;
    if (i < n4) {
        float4 v = src[i];
        __half2 h0 = __floats2half2_rn(v.x, v.y);
        __half2 h1 = __floats2half2_rn(v.z, v.w);
        uint2 o;
        o.x = *reinterpret_cast<uint32_t*>(&h0);
        o.y = *reinterpret_cast<uint32_t*>(&h1);
        dst[i] = o;
    }
}

// ---------------- prepass: transpose f32[R][C] -> fp16[C][R], 64x64 tiles ----
// float4 coalesced reads; float2 conflict-free SMEM reads; half2 coalesced writes.
__global__ void __launch_bounds__(256)
k_trh64(const float* __restrict__ src, __half* __restrict__ dst, int R, int C) {
    __shared__ float sm[64][66];           // [c][r], pad 66 -> 8B-aligned rows
    int z = blockIdx.z;
    src += (size_t)z * R * C;
    dst += (size_t)z * R * C;
    int c0 = blockIdx.x * 64, r0 = blockIdx.y * 64;
    int tid = threadIdx.x;

    // load 64r x 64c as float4, scatter into transposed smem
    int lr = tid >> 4, lc4 = tid & 15;
#pragma unroll
    for (int p = 0; p < 4; p++) {
        int r = lr + p * 16;
        float4 v = *reinterpret_cast<const float4*>(&src[(size_t)(r0 + r) * C + c0 + lc4 * 4]);
        sm[lc4 * 4 + 0][r] = v.x;
        sm[lc4 * 4 + 1][r] = v.y;
        sm[lc4 * 4 + 2][r] = v.z;
        sm[lc4 * 4 + 3][r] = v.w;
    }
    __syncthreads();

    // store 64c rows of 64r as half2 (float2 LDS, conflict-free)
    int sc = tid >> 5, sr2 = tid & 31;
#pragma unroll
    for (int p = 0; p < 8; p++) {
        int c = sc + p * 8;
        float2 v = *reinterpret_cast<const float2*>(&sm[c][sr2 * 2]);
        __half2 h = __floats2half2_rn(v.x, v.y);
        *reinterpret_cast<__half2*>(&dst[(size_t)(c0 + c) * R + r0 + sr2 * 2]) = h;
    }
}

// ---------------- init / router / scan / scatter -----------------------------
__global__ void k_init() {
    int i = blockIdx.x * blockDim.x + threadIdx.x;
    if (i < ENUM) g_counts[i] = 0;
    for (int j = i; j < SH0; j += gridDim.x * blockDim.x) g_token_list[j] = -1;
    for (int j = i; j < TNUM; j += gridDim.x * blockDim.x) g_token_list[SH0 + j] = j;
}

__global__ void k_router(const float* __restrict__ x,
                         const float* __restrict__ gate_w,
                         const float* __restrict__ sgw) {
    int t = blockIdx.x;
    const float* xr = x + (size_t)t * DDIM;
    float acc[17];
#pragma unroll
    for (int e = 0; e < 17; e++) acc[e] = 0.f;
    for (int d = threadIdx.x; d < DDIM; d += blockDim.x) {
        float xv = xr[d];
#pragma unroll
        for (int e = 0; e < ENUM; e++) acc[e] += xv * gate_w[e * DDIM + d];
        acc[16] += xv * sgw[d];
    }
#pragma unroll
    for (int off = 16; off; off >>= 1)
#pragma unroll
        for (int e = 0; e < 17; e++) acc[e] += __shfl_down_sync(0xffffffffu, acc[e], off);
    __shared__ float red[17][4];
    int warp = threadIdx.x >> 5, lane = threadIdx.x & 31;
    if (lane == 0)
#pragma unroll
        for (int e = 0; e < 17; e++) red[e][warp] = acc[e];
    __syncthreads();
    if (threadIdx.x == 0) {
        float v[17];
#pragma unroll
        for (int e = 0; e < 17; e++) v[e] = red[e][0] + red[e][1] + red[e][2] + red[e][3];
        float lv[16];
#pragma unroll
        for (int e = 0; e < ENUM; e++) lv[e] = v[e];
        int idx[TOPK]; float lg[TOPK];
#pragma unroll
        for (int k = 0; k < TOPK; k++) {
            int bi = 0; float bv = lv[0];
#pragma unroll
            for (int e = 1; e < ENUM; e++) if (lv[e] > bv) { bv = lv[e]; bi = e; }
            idx[k] = bi; lg[k] = bv; lv[bi] = -1e30f;
        }
        float mx = lg[0], s = 0.f, w[TOPK];
#pragma unroll
        for (int k = 0; k < TOPK; k++) { w[k] = expf(lg[k] - mx); s += w[k]; }
        float inv = 1.f / s;
#pragma unroll
        for (int k = 0; k < TOPK; k++) {
            g_topk[t * TOPK + k]   = idx[k];
            g_comb_w[t * TOPK + k] = w[k] * inv;
            atomicAdd(&g_counts[idx[k]], 1);
        }
        g_weight_list[SH0 + t] = 1.f / (1.f + expf(-v[16]));
    }
}

__global__ void k_scan() {
    if (threadIdx.x == 0 && blockIdx.x == 0) {
        int o = 0, nt = 0;
        for (int e = 0; e < ENUM; e++) {
            g_offsets[e] = o;
            g_cursor[e]  = o;
            int c = (g_counts[e] + MT - 1) & ~(MT - 1);
            for (int r = 0; r < c; r += MT) { g_tile_seg[nt] = e; g_tile_r0[nt] = o + r; nt++; }
            o += c;
        }
        g_offsets[ENUM] = o;
        for (int r = 0; r < TNUM; r += MT) { g_tile_seg[nt] = ENUM; g_tile_r0[nt] = SH0 + r; nt++; }
        g_ntiles = nt;
    }
}

__global__ void k_scatter() {
    int i = blockIdx.x * blockDim.x + threadIdx.x;
    if (i < TNUM * TOPK) {
        int e = g_topk[i];
        int pos = atomicAdd(&g_cursor[e], 1);
        g_token_list[pos]  = i / TOPK;
        g_weight_list[pos] = g_comb_w[i];
        g_pos_of[i]        = pos;
    }
}

// ---------------- SMEM geometry ----------------------------------------------
// rows of 32 fp16 (64B) padded to 80B (20 words) -> conflict-free 20g+t banking
#define ROWB   80
#define ROWW   20
#define UA_BUF (128 * ROWB)                 // 10240 B
#define UB_BUF (64 * ROWB)                  // 5120 B
#define U_SMEM (2 * UA_BUF + 4 * UB_BUF)    // 40960 B
#define DB_BUF (128 * ROWB)                 // 10240 B
#define D_SMEM (2 * UA_BUF + 2 * DB_BUF)    // 40960 B

// ---------------- upgate: H = silu(X@Wg) * (X@Wu)  (fp16 m16n8k16) -----------
// Block 128 x 64(F). 8 warps = 4(M) x 2(F); warp 32x32 per matrix.
__global__ void __launch_bounds__(256, 2)
k_upgate() {
    int ti = blockIdx.x;
    if (ti >= g_ntiles) return;
    int z  = g_tile_seg[ti];
    int r0 = g_tile_r0[ti];
    int f0 = blockIdx.y * 64;

    const __half* Wg = (z == ENUM) ? g_sWgt : g_Wgt + (size_t)z * FDIM * DDIM;
    const __half* Wu = (z == ENUM) ? g_sWut : g_Wut + (size_t)z * FDIM * DDIM;

    extern __shared__ char smc[];
    uint32_t smb = smem_u32(smc);
    __shared__ int s_tok[MT];

    int tid = threadIdx.x, lane = tid & 31;
    int warp = tid >> 5, wm = warp & 3, wf = warp >> 2;
    int g = lane >> 2, t = lane & 3;

    if (tid < MT) s_tok[tid] = g_token_list[r0 + tid];
    __syncthreads();

    float Cg[2][4][4], Cu[2][4][4];
#pragma unroll
    for (int mt = 0; mt < 2; mt++)
#pragma unroll
        for (int nt = 0; nt < 4; nt++)
#pragma unroll
            for (int q = 0; q < 4; q++) { Cg[mt][nt][q] = 0.f; Cu[mt][nt][q] = 0.f; }

#define U_LOAD(i)                                                               \
    do {                                                                        \
        int s_ = (i) & 1;                                                       \
        uint32_t a_  = smb + s_ * UA_BUF;                                       \
        uint32_t bg_ = smb + 2 * UA_BUF + s_ * UB_BUF;                          \
        uint32_t bu_ = smb + 2 * UA_BUF + 2 * UB_BUF + s_ * UB_BUF;             \
        _Pragma("unroll")                                                       \
        for (int p = 0; p < 2; p++) {                                           \
            int idx = tid + p * 256;                                            \
            int row = idx >> 2, ch = idx & 3;                                   \
            int tok = s_tok[row];                                               \
            cpa16(a_ + row * ROWB + ch * 16,                                    \
                  g_Xh + (size_t)(tok < 0 ? 0 : tok) * DDIM + (i) * 32 + ch * 8,\
                  tok >= 0);                                                    \
        }                                                                       \
        {                                                                       \
            int row = tid >> 2, ch = tid & 3;                                   \
            cpa16(bg_ + row * ROWB + ch * 16,                                   \
                  Wg + (size_t)(f0 + row) * DDIM + (i) * 32 + ch * 8, true);    \
            cpa16(bu_ + row * ROWB + ch * 16,                                   \
                  Wu + (size_t)(f0 + row) * DDIM + (i) * 32 + ch * 8, true);    \
        }                                                                       \
        CP_COMMIT();                                                            \
    } while (0)

    const int NIT = DDIM / 32;   // 64
    U_LOAD(0);
    U_LOAD(1);
    for (int i = 0; i < NIT; i++) {
        if (i + 1 < NIT) CP_WAIT(1); else CP_WAIT(0);
        __syncthreads();
        int s = i & 1;
        const uint32_t* As32 = (const uint32_t*)(smc + s * UA_BUF);
        const uint32_t* Bg32 = (const uint32_t*)(smc + 2 * UA_BUF + s * UB_BUF);
        const uint32_t* Bu32 = (const uint32_t*)(smc + 2 * UA_BUF + 2 * UB_BUF + s * UB_BUF);
#pragma unroll
        for (int s2 = 0; s2 < 2; s2++) {
            int kw = s2 * 8 + t;
            uint32_t a[2][4];
#pragma unroll
            for (int mt = 0; mt < 2; mt++) {
                const uint32_t* ar = As32 + (wm * 32 + mt * 16 + g) * ROWW + kw;
                a[mt][0] = ar[0];
                a[mt][1] = ar[8 * ROWW];
                a[mt][2] = ar[4];
                a[mt][3] = ar[8 * ROWW + 4];
            }
#pragma unroll
            for (int nt = 0; nt < 4; nt++) {
                int n = wf * 32 + nt * 8 + g;
                const uint32_t* bp = Bg32 + n * ROWW + kw;
                uint32_t b0 = bp[0], b1 = bp[4];
                MMA_F16(Cg[0][nt], a[0], b0, b1);
                MMA_F16(Cg[1][nt], a[1], b0, b1);
                bp = Bu32 + n * ROWW + kw;
                b0 = bp[0]; b1 = bp[4];
                MMA_F16(Cu[0][nt], a[0], b0, b1);
                MMA_F16(Cu[1][nt], a[1], b0, b1);
            }
        }
        __syncthreads();
        if (i + 2 < NIT) U_LOAD(i + 2);
    }
#undef U_LOAD

    // epilogue: SwiGLU in-register, half2 store into natural H layout
#pragma unroll
    for (int mt = 0; mt < 2; mt++) {
        int m0 = r0 + wm * 32 + mt * 16 + g;
#pragma unroll
        for (int nt = 0; nt < 4; nt++) {
            int fb = f0 + wf * 32 + nt * 8 + 2 * t;
            __half2 h;
            h = __floats2half2_rn(silu_mul(Cg[mt][nt][0], Cu[mt][nt][0]),
                                  silu_mul(Cg[mt][nt][1], Cu[mt][nt][1]));
            *reinterpret_cast<__half2*>(g_Hh + (size_t)m0 * FDIM + fb) = h;
            h = __floats2half2_rn(silu_mul(Cg[mt][nt][2], Cu[mt][nt][2]),
                                  silu_mul(Cg[mt][nt][3], Cu[mt][nt][3]));
            *reinterpret_cast<__half2*>(g_Hh + (size_t)(m0 + 8) * FDIM + fb) = h;
        }
    }
}

// ---------------- down: partial = w * (H @ Wd)  (fp16 m16n8k16) --------------
// Block 128 x 128(D). 8 warps = 4(M) x 2(N); warp 32x64.
__global__ void __launch_bounds__(256, 2)
k_down() {
    int ti = blockIdx.x;
    if (ti >= g_ntiles) return;
    int z  = g_tile_seg[ti];
    int r0 = g_tile_r0[ti];
    int n0 = blockIdx.y * 128;

    const __half* Wd = (z == ENUM) ? g_sWdt : g_Wdt + (size_t)z * DDIM * FDIM;

    extern __shared__ char smc[];
    uint32_t smb = smem_u32(smc);

    int tid = threadIdx.x, lane = tid & 31;
    int warp = tid >> 5, wm = warp & 3, wn = warp >> 2;
    int g = lane >> 2, t = lane & 3;

    float C[2][8][4];
#pragma unroll
    for (int mt = 0; mt < 2; mt++)
#pragma unroll
        for (int nt = 0; nt < 8; nt++)
#pragma unroll
            for (int q = 0; q < 4; q++) C[mt][nt][q] = 0.f;

#define D_LOAD(i)                                                               \
    do {                                                                        \
        int s_ = (i) & 1;                                                       \
        uint32_t a_ = smb + s_ * UA_BUF;                                        \
        uint32_t b_ = smb + 2 * UA_BUF + s_ * DB_BUF;                           \
        _Pragma("unroll")                                                       \
        for (int p = 0; p < 2; p++) {                                           \
            int idx = tid + p * 256;                                            \
            int row = idx >> 2, ch = idx & 3;                                   \
            cpa16(a_ + row * ROWB + ch * 16,                                    \
                  g_Hh + (size_t)(r0 + row) * FDIM + (i) * 32 + ch * 8, true);  \
            cpa16(b_ + row * ROWB + ch * 16,                                    \
                  Wd + (size_t)(n0 + row) * FDIM + (i) * 32 + ch * 8, true);    \
        }                                                                       \
        CP_COMMIT();                                                            \
    } while (0)

    const int NIT = FDIM / 32;   // 16
    D_LOAD(0);
    D_LOAD(1);
    for (int i = 0; i < NIT; i++) {
        if (i + 1 < NIT) CP_WAIT(1); else CP_WAIT(0);
        __syncthreads();
        int s = i & 1;
        const uint32_t* As32 = (const uint32_t*)(smc + s * UA_BUF);
        const uint32_t* Bs32 = (const uint32_t*)(smc + 2 * UA_BUF + s * DB_BUF);
#pragma unroll
        for (int s2 = 0; s2 < 2; s2++) {
            int kw = s2 * 8 + t;
            uint32_t a[2][4];
#pragma unroll
            for (int mt = 0; mt < 2; mt++) {
                const uint32_t* ar = As32 + (wm * 32 + mt * 16 + g) * ROWW + kw;
                a[mt][0] = ar[0];
                a[mt][1] = ar[8 * ROWW];
                a[mt][2] = ar[4];
                a[mt][3] = ar[8 * ROWW + 4];
            }
#pragma unroll
            for (int nt = 0; nt < 8; nt++) {
                int n = wn * 64 + nt * 8 + g;
                const uint32_t* bp = Bs32 + n * ROWW + kw;
                uint32_t b0 = bp[0], b1 = bp[4];
                MMA_F16(C[0][nt], a[0], b0, b1);
                MMA_F16(C[1][nt], a[1], b0, b1);
            }
        }
        __syncthreads();
        if (i + 2 < NIT) D_LOAD(i + 2);
    }
#undef D_LOAD

    // epilogue: scale by routing/shared weight, store f32 partial rows
#pragma unroll
    for (int mt = 0; mt < 2; mt++) {
        int m0 = r0 + wm * 32 + mt * 16 + g;
        float w0 = g_weight_list[m0];
        float w1 = g_weight_list[m0 + 8];
#pragma unroll
        for (int nt = 0; nt < 8; nt++) {
            int n = n0 + wn * 64 + nt * 8 + t * 2;
            float2 v;
            v.x = w0 * C[mt][nt][0];
            v.y = w0 * C[mt][nt][1];
            *reinterpret_cast<float2*>(g_partial + (size_t)m0 * DDIM + n) = v;
            v.x = w1 * C[mt][nt][2];
            v.y = w1 * C[mt][nt][3];
            *reinterpret_cast<float2*>(g_partial + (size_t)(m0 + 8) * DDIM + n) = v;
        }
    }
}

// ---------------- combine ----------------------------------------------------
__global__ void k_combine(float* __restrict__ out) {
    int t = blockIdx.x;
    int p0 = g_pos_of[t * TOPK + 0];
    int p1 = g_pos_of[t * TOPK + 1];
    int p2 = g_pos_of[t * TOPK + 2];
    int p3 = g_pos_of[t * TOPK + 3];
    const float4* a0 = (const float4*)(g_partial + (size_t)p0 * DDIM);
    const float4* a1 = (const float4*)(g_partial + (size_t)p1 * DDIM);
    const float4* a2 = (const float4*)(g_partial + (size_t)p2 * DDIM);
    const float4* a3 = (const float4*)(g_partial + (size_t)p3 * DDIM);
    const float4* as = (const float4*)(g_partial + (size_t)(SH0 + t) * DDIM);
    float4* o = (float4*)(out + (size_t)t * DDIM);
    for (int d = threadIdx.x; d < DDIM / 4; d += blockDim.x) {
        float4 v0 = a0[d], v1 = a1[d], v2 = a2[d], v3 = a3[d], vs = as[d];
        float4 r;
        r.x = v0.x + v1.x + v2.x + v3.x + vs.x;
        r.y = v0.y + v1.y + v2.y + v3.y + vs.y;
        r.z = v0.z + v1.z + v2.z + v3.z + vs.z;
        r.w = v0.w + v1.w + v2.w + v3.w + vs.w;
        o[d] = r;
    }
}

// ---------------- launch ------------------------------------------------------
extern "C" void kernel_launch(void* const* d_in, const int* in_sizes, int n_in,
                              void* d_out, int out_size) {
    const float* x   = (const float*)d_in[0];
    const float* gw  = (const float*)d_in[1];
    const float* Wg  = (const float*)d_in[2];
    const float* Wu  = (const float*)d_in[3];
    const float* Wd  = (const float*)d_in[4];
    const float* sWg = (const float*)d_in[5];
    const float* sWu = (const float*)d_in[6];
    const float* sWd = (const float*)d_in[7];
    const float* sgw = (const float*)d_in[8];
    float* out = (float*)d_out;
    (void)in_sizes; (void)n_in; (void)out_size;

    __half *xh, *wgt, *wut, *wdt, *swgt, *swut, *swdt;
    cudaGetSymbolAddress((void**)&xh,   g_Xh);
    cudaGetSymbolAddress((void**)&wgt,  g_Wgt);
    cudaGetSymbolAddress((void**)&wut,  g_Wut);
    cudaGetSymbolAddress((void**)&wdt,  g_Wdt);
    cudaGetSymbolAddress((void**)&swgt, g_sWgt);
    cudaGetSymbolAddress((void**)&swut, g_sWut);
    cudaGetSymbolAddress((void**)&swdt, g_sWdt);

    // X: flat f32 -> fp16
    const int XN4 = TNUM * DDIM / 4;
    k_cvth<<<(XN4 + 255) / 256, 256>>>((const float4*)x, (uint2*)xh, XN4);
    // Weights: 64x64 transpose + fp16 round. Wg/Wu [D][F] -> [F][D]; Wd [F][D] -> [D][F]
    k_trh64<<<dim3(FDIM / 64, DDIM / 64, ENUM), 256>>>(Wg,  wgt,  DDIM, FDIM);
    k_trh64<<<dim3(FDIM / 64, DDIM / 64, ENUM), 256>>>(Wu,  wut,  DDIM, FDIM);
    k_trh64<<<dim3(DDIM / 64, FDIM / 64, ENUM), 256>>>(Wd,  wdt,  FDIM, DDIM);
    k_trh64<<<dim3(FDIM / 64, DDIM / 64, 1),    256>>>(sWg, swgt, DDIM, FDIM);
    k_trh64<<<dim3(FDIM / 64, DDIM / 64, 1),    256>>>(sWu, swut, DDIM, FDIM);
    k_trh64<<<dim3(DDIM / 64, FDIM / 64, 1),    256>>>(sWd, swdt, FDIM, DDIM);

    k_init<<<8, 256>>>();
    k_router<<<TNUM, 128>>>(x, gw, sgw);
    k_scan<<<1, 1>>>();
    k_scatter<<<(TNUM * TOPK + 255) / 256, 256>>>();

    k_upgate<<<dim3(MAXT, FDIM / 64), 256, U_SMEM>>>();
    k_down<<<dim3(MAXT, DDIM / 128), 256, D_SMEM>>>();
    k_combine<<<TNUM, 256>>>(out);
}

// round 14
// speedup vs baseline: 1.9769x; 1.0197x over previous
#include <cuda_runtime.h>
#include <cuda_fp16.h>
#include <math.h>
#include <stdint.h>

#define TNUM 2048
#define DDIM 2048
#define FDIM 512
#define ENUM 16
#define TOPK 4
#define MT   128
#define SH0  (TNUM * TOPK + ENUM * MT)   // 10240
#define HROWS (SH0 + TNUM)               // 12288
#define MAXT (HROWS / MT)                // 96

// ---------------- device scratch -------------------------------------------
__device__ float g_comb_w[TNUM * TOPK];
__device__ int   g_topk[TNUM * TOPK];
__device__ int   g_counts[ENUM];
__device__ int   g_offsets[ENUM + 1];
__device__ int   g_cursor[ENUM];
__device__ int   g_token_list[HROWS];
__device__ float g_weight_list[HROWS];
__device__ int   g_pos_of[TNUM * TOPK];
__device__ int   g_tile_seg[MAXT];
__device__ int   g_tile_r0[MAXT];
__device__ int   g_ntiles;
__device__ __half g_partialh[(size_t)HROWS * DDIM];         // fp16 partial rows
// fp16 operands
__device__ __half g_Xh[(size_t)TNUM * DDIM];                // [m][D]
__device__ __half g_Hh[(size_t)HROWS * FDIM];               // [row][F]
__device__ __half g_Wgt[(size_t)ENUM * FDIM * DDIM];        // [F][D] K-major
__device__ __half g_Wut[(size_t)ENUM * FDIM * DDIM];
__device__ __half g_Wdt[(size_t)ENUM * DDIM * FDIM];        // [D][F] K-major
__device__ __half g_sWgt[(size_t)FDIM * DDIM];
__device__ __half g_sWut[(size_t)FDIM * DDIM];
__device__ __half g_sWdt[(size_t)DDIM * FDIM];

// ---------------- helpers ----------------------------------------------------
__device__ __forceinline__ uint32_t smem_u32(const void* p) {
    uint32_t a;
    asm("{ .reg .u64 t; cvta.to.shared.u64 t, %1; cvt.u32.u64 %0, t; }" : "=r"(a) : "l"(p));
    return a;
}
__device__ __forceinline__ void cpa16(uint32_t dst, const void* src, bool valid) {
    int sz = valid ? 16 : 0;
    asm volatile("cp.async.cg.shared.global [%0], [%1], 16, %2;"
                 :: "r"(dst), "l"(src), "r"(sz) : "memory");
}
#define CP_COMMIT() asm volatile("cp.async.commit_group;" ::: "memory")
#define CP_WAIT(n)  asm volatile("cp.async.wait_group %0;" :: "n"(n) : "memory")

// m16n8k16 fp16 -> f32 accumulate
#define MMA_F16(C, A, b0, b1)                                                   \
    asm volatile("mma.sync.aligned.m16n8k16.row.col.f32.f16.f16.f32 "           \
                 "{%0,%1,%2,%3}, {%4,%5,%6,%7}, {%8,%9}, {%0,%1,%2,%3};"        \
                 : "+f"((C)[0]), "+f"((C)[1]), "+f"((C)[2]), "+f"((C)[3])       \
                 : "r"((A)[0]), "r"((A)[1]), "r"((A)[2]), "r"((A)[3]),          \
                   "r"(b0), "r"(b1))

__device__ __forceinline__ float silu_mul(float g, float u) {
    return g / (1.f + expf(-g)) * u;
}

// ---------------- prepass: f32 -> fp16 (flat) --------------------------------
__global__ void k_cvth(const float4* __restrict__ src, uint2* __restrict__ dst, int n4) {
    int i = blockIdx.x * blockDim.x + threadIdx.x;
    if (i < n4) {
        float4 v = src[i];
        __half2 h0 = __floats2half2_rn(v.x, v.y);
        __half2 h1 = __floats2half2_rn(v.z, v.w);
        uint2 o;
        o.x = *reinterpret_cast<uint32_t*>(&h0);
        o.y = *reinterpret_cast<uint32_t*>(&h1);
        dst[i] = o;
    }
}

// ---------------- prepass: transpose f32[R][C] -> fp16[C][R], 64x64 tiles ----
// XOR-swizzled SMEM: word(c,r) = c*64 + (r ^ (2*(c>>2) & 31)).
// Store phase: 32 distinct banks. Read phase: float2, pair-adjacent, 2-phase min.
__global__ void __launch_bounds__(256)
k_trh64(const float* __restrict__ src, __half* __restrict__ dst, int R, int C) {
    __shared__ float sm[64 * 64];
    int z = blockIdx.z;
    src += (size_t)z * R * C;
    dst += (size_t)z * R * C;
    int c0 = blockIdx.x * 64, r0 = blockIdx.y * 64;
    int tid = threadIdx.x;

    // load 64r x 64c as float4, scatter into swizzled transposed smem
    int lr = tid >> 4, lc4 = tid & 15;
    int perm_s = (2 * lc4) & 31;                  // perm(c)=2*(c>>2)&31, c=4*lc4+j
#pragma unroll
    for (int p = 0; p < 4; p++) {
        int r = lr + p * 16;
        float4 v = *reinterpret_cast<const float4*>(&src[(size_t)(r0 + r) * C + c0 + lc4 * 4]);
        int rs = r ^ perm_s;
        sm[(lc4 * 4 + 0) * 64 + rs] = v.x;
        sm[(lc4 * 4 + 1) * 64 + rs] = v.y;
        sm[(lc4 * 4 + 2) * 64 + rs] = v.z;
        sm[(lc4 * 4 + 3) * 64 + rs] = v.w;
    }
    __syncthreads();

    // store 64c rows of 64r as half2 (float2 LDS at swizzled offsets)
    int sc = tid >> 5, sr2 = tid & 31;
#pragma unroll
    for (int p = 0; p < 8; p++) {
        int c = sc + p * 8;
        int perm = (2 * (c >> 2)) & 31;
        float2 v = *reinterpret_cast<const float2*>(&sm[c * 64 + ((sr2 * 2) ^ perm)]);
        __half2 h = __floats2half2_rn(v.x, v.y);
        *reinterpret_cast<__half2*>(&dst[(size_t)(c0 + c) * R + r0 + sr2 * 2]) = h;
    }
}

// ---------------- init / router / scan / scatter -----------------------------
__global__ void k_init() {
    int i = blockIdx.x * blockDim.x + threadIdx.x;
    if (i < ENUM) g_counts[i] = 0;
    for (int j = i; j < SH0; j += gridDim.x * blockDim.x) g_token_list[j] = -1;
    for (int j = i; j < TNUM; j += gridDim.x * blockDim.x) g_token_list[SH0 + j] = j;
}

__global__ void k_router(const float* __restrict__ x,
                         const float* __restrict__ gate_w,
                         const float* __restrict__ sgw) {
    int t = blockIdx.x;
    const float* xr = x + (size_t)t * DDIM;
    float acc[17];
#pragma unroll
    for (int e = 0; e < 17; e++) acc[e] = 0.f;
    for (int d = threadIdx.x; d < DDIM; d += blockDim.x) {
        float xv = xr[d];
#pragma unroll
        for (int e = 0; e < ENUM; e++) acc[e] += xv * gate_w[e * DDIM + d];
        acc[16] += xv * sgw[d];
    }
#pragma unroll
    for (int off = 16; off; off >>= 1)
#pragma unroll
        for (int e = 0; e < 17; e++) acc[e] += __shfl_down_sync(0xffffffffu, acc[e], off);
    __shared__ float red[17][4];
    int warp = threadIdx.x >> 5, lane = threadIdx.x & 31;
    if (lane == 0)
#pragma unroll
        for (int e = 0; e < 17; e++) red[e][warp] = acc[e];
    __syncthreads();
    if (threadIdx.x == 0) {
        float v[17];
#pragma unroll
        for (int e = 0; e < 17; e++) v[e] = red[e][0] + red[e][1] + red[e][2] + red[e][3];
        float lv[16];
#pragma unroll
        for (int e = 0; e < ENUM; e++) lv[e] = v[e];
        int idx[TOPK]; float lg[TOPK];
#pragma unroll
        for (int k = 0; k < TOPK; k++) {
            int bi = 0; float bv = lv[0];
#pragma unroll
            for (int e = 1; e < ENUM; e++) if (lv[e] > bv) { bv = lv[e]; bi = e; }
            idx[k] = bi; lg[k] = bv; lv[bi] = -1e30f;
        }
        float mx = lg[0], s = 0.f, w[TOPK];
#pragma unroll
        for (int k = 0; k < TOPK; k++) { w[k] = expf(lg[k] - mx); s += w[k]; }
        float inv = 1.f / s;
#pragma unroll
        for (int k = 0; k < TOPK; k++) {
            g_topk[t * TOPK + k]   = idx[k];
            g_comb_w[t * TOPK + k] = w[k] * inv;
            atomicAdd(&g_counts[idx[k]], 1);
        }
        g_weight_list[SH0 + t] = 1.f / (1.f + expf(-v[16]));
    }
}

__global__ void k_scan() {
    if (threadIdx.x == 0 && blockIdx.x == 0) {
        int o = 0, nt = 0;
        for (int e = 0; e < ENUM; e++) {
            g_offsets[e] = o;
            g_cursor[e]  = o;
            int c = (g_counts[e] + MT - 1) & ~(MT - 1);
            for (int r = 0; r < c; r += MT) { g_tile_seg[nt] = e; g_tile_r0[nt] = o + r; nt++; }
            o += c;
        }
        g_offsets[ENUM] = o;
        for (int r = 0; r < TNUM; r += MT) { g_tile_seg[nt] = ENUM; g_tile_r0[nt] = SH0 + r; nt++; }
        g_ntiles = nt;
    }
}

__global__ void k_scatter() {
    int i = blockIdx.x * blockDim.x + threadIdx.x;
    if (i < TNUM * TOPK) {
        int e = g_topk[i];
        int pos = atomicAdd(&g_cursor[e], 1);
        g_token_list[pos]  = i / TOPK;
        g_weight_list[pos] = g_comb_w[i];
        g_pos_of[i]        = pos;
    }
}

// ---------------- SMEM geometry ----------------------------------------------
// rows of 32 fp16 (64B) padded to 80B (20 words) -> conflict-free 20g+t banking
#define ROWB   80
#define ROWW   20
#define UA_BUF (128 * ROWB)                 // 10240 B
#define UB_BUF (64 * ROWB)                  // 5120 B
#define U_SMEM (2 * UA_BUF + 4 * UB_BUF)    // 40960 B
#define DB_BUF (128 * ROWB)                 // 10240 B
#define D_SMEM (2 * UA_BUF + 2 * DB_BUF)    // 40960 B

// ---------------- upgate: H = silu(X@Wg) * (X@Wu)  (fp16 m16n8k16) -----------
// Block 128 x 64(F). 8 warps = 4(M) x 2(F); warp 32x32 per matrix.
__global__ void __launch_bounds__(256, 2)
k_upgate() {
    int ti = blockIdx.x;
    if (ti >= g_ntiles) return;
    int z  = g_tile_seg[ti];
    int r0 = g_tile_r0[ti];
    int f0 = blockIdx.y * 64;

    const __half* Wg = (z == ENUM) ? g_sWgt : g_Wgt + (size_t)z * FDIM * DDIM;
    const __half* Wu = (z == ENUM) ? g_sWut : g_Wut + (size_t)z * FDIM * DDIM;

    extern __shared__ char smc[];
    uint32_t smb = smem_u32(smc);
    __shared__ int s_tok[MT];

    int tid = threadIdx.x, lane = tid & 31;
    int warp = tid >> 5, wm = warp & 3, wf = warp >> 2;
    int g = lane >> 2, t = lane & 3;

    if (tid < MT) s_tok[tid] = g_token_list[r0 + tid];
    __syncthreads();

    float Cg[2][4][4], Cu[2][4][4];
#pragma unroll
    for (int mt = 0; mt < 2; mt++)
#pragma unroll
        for (int nt = 0; nt < 4; nt++)
#pragma unroll
            for (int q = 0; q < 4; q++) { Cg[mt][nt][q] = 0.f; Cu[mt][nt][q] = 0.f; }

#define U_LOAD(i)                                                               \
    do {                                                                        \
        int s_ = (i) & 1;                                                       \
        uint32_t a_  = smb + s_ * UA_BUF;                                       \
        uint32_t bg_ = smb + 2 * UA_BUF + s_ * UB_BUF;                          \
        uint32_t bu_ = smb + 2 * UA_BUF + 2 * UB_BUF + s_ * UB_BUF;             \
        _Pragma("unroll")                                                       \
        for (int p = 0; p < 2; p++) {                                           \
            int idx = tid + p * 256;                                            \
            int row = idx >> 2, ch = idx & 3;                                   \
            int tok = s_tok[row];                                               \
            cpa16(a_ + row * ROWB + ch * 16,                                    \
                  g_Xh + (size_t)(tok < 0 ? 0 : tok) * DDIM + (i) * 32 + ch * 8,\
                  tok >= 0);                                                    \
        }                                                                       \
        {                                                                       \
            int row = tid >> 2, ch = tid & 3;                                   \
            cpa16(bg_ + row * ROWB + ch * 16,                                   \
                  Wg + (size_t)(f0 + row) * DDIM + (i) * 32 + ch * 8, true);    \
            cpa16(bu_ + row * ROWB + ch * 16,                                   \
                  Wu + (size_t)(f0 + row) * DDIM + (i) * 32 + ch * 8, true);    \
        }                                                                       \
        CP_COMMIT();                                                            \
    } while (0)

    const int NIT = DDIM / 32;   // 64
    U_LOAD(0);
    U_LOAD(1);
    for (int i = 0; i < NIT; i++) {
        if (i + 1 < NIT) CP_WAIT(1); else CP_WAIT(0);
        __syncthreads();
        int s = i & 1;
        const uint32_t* As32 = (const uint32_t*)(smc + s * UA_BUF);
        const uint32_t* Bg32 = (const uint32_t*)(smc + 2 * UA_BUF + s * UB_BUF);
        const uint32_t* Bu32 = (const uint32_t*)(smc + 2 * UA_BUF + 2 * UB_BUF + s * UB_BUF);
#pragma unroll
        for (int s2 = 0; s2 < 2; s2++) {
            int kw = s2 * 8 + t;
            uint32_t a[2][4];
#pragma unroll
            for (int mt = 0; mt < 2; mt++) {
                const uint32_t* ar = As32 + (wm * 32 + mt * 16 + g) * ROWW + kw;
                a[mt][0] = ar[0];
                a[mt][1] = ar[8 * ROWW];
                a[mt][2] = ar[4];
                a[mt][3] = ar[8 * ROWW + 4];
            }
#pragma unroll
            for (int nt = 0; nt < 4; nt++) {
                int n = wf * 32 + nt * 8 + g;
                const uint32_t* bp = Bg32 + n * ROWW + kw;
                uint32_t b0 = bp[0], b1 = bp[4];
                MMA_F16(Cg[0][nt], a[0], b0, b1);
                MMA_F16(Cg[1][nt], a[1], b0, b1);
                bp = Bu32 + n * ROWW + kw;
                b0 = bp[0]; b1 = bp[4];
                MMA_F16(Cu[0][nt], a[0], b0, b1);
                MMA_F16(Cu[1][nt], a[1], b0, b1);
            }
        }
        __syncthreads();
        if (i + 2 < NIT) U_LOAD(i + 2);
    }
#undef U_LOAD

    // epilogue: SwiGLU in-register, half2 store into natural H layout
#pragma unroll
    for (int mt = 0; mt < 2; mt++) {
        int m0 = r0 + wm * 32 + mt * 16 + g;
#pragma unroll
        for (int nt = 0; nt < 4; nt++) {
            int fb = f0 + wf * 32 + nt * 8 + 2 * t;
            __half2 h;
            h = __floats2half2_rn(silu_mul(Cg[mt][nt][0], Cu[mt][nt][0]),
                                  silu_mul(Cg[mt][nt][1], Cu[mt][nt][1]));
            *reinterpret_cast<__half2*>(g_Hh + (size_t)m0 * FDIM + fb) = h;
            h = __floats2half2_rn(silu_mul(Cg[mt][nt][2], Cu[mt][nt][2]),
                                  silu_mul(Cg[mt][nt][3], Cu[mt][nt][3]));
            *reinterpret_cast<__half2*>(g_Hh + (size_t)(m0 + 8) * FDIM + fb) = h;
        }
    }
}

// ---------------- down: partial = w * (H @ Wd)  (fp16 m16n8k16) --------------
// Block 128 x 128(D). 8 warps = 4(M) x 2(N); warp 32x64.
__global__ void __launch_bounds__(256, 2)
k_down() {
    int ti = blockIdx.x;
    if (ti >= g_ntiles) return;
    int z  = g_tile_seg[ti];
    int r0 = g_tile_r0[ti];
    int n0 = blockIdx.y * 128;

    const __half* Wd = (z == ENUM) ? g_sWdt : g_Wdt + (size_t)z * DDIM * FDIM;

    extern __shared__ char smc[];
    uint32_t smb = smem_u32(smc);

    int tid = threadIdx.x, lane = tid & 31;
    int warp = tid >> 5, wm = warp & 3, wn = warp >> 2;
    int g = lane >> 2, t = lane & 3;

    float C[2][8][4];
#pragma unroll
    for (int mt = 0; mt < 2; mt++)
#pragma unroll
        for (int nt = 0; nt < 8; nt++)
#pragma unroll
            for (int q = 0; q < 4; q++) C[mt][nt][q] = 0.f;

#define D_LOAD(i)                                                               \
    do {                                                                        \
        int s_ = (i) & 1;                                                       \
        uint32_t a_ = smb + s_ * UA_BUF;                                        \
        uint32_t b_ = smb + 2 * UA_BUF + s_ * DB_BUF;                           \
        _Pragma("unroll")                                                       \
        for (int p = 0; p < 2; p++) {                                           \
            int idx = tid + p * 256;                                            \
            int row = idx >> 2, ch = idx & 3;                                   \
            cpa16(a_ + row * ROWB + ch * 16,                                    \
                  g_Hh + (size_t)(r0 + row) * FDIM + (i) * 32 + ch * 8, true);  \
            cpa16(b_ + row * ROWB + ch * 16,                                    \
                  Wd + (size_t)(n0 + row) * FDIM + (i) * 32 + ch * 8, true);    \
        }                                                                       \
        CP_COMMIT();                                                            \
    } while (0)

    const int NIT = FDIM / 32;   // 16
    D_LOAD(0);
    D_LOAD(1);
    for (int i = 0; i < NIT; i++) {
        if (i + 1 < NIT) CP_WAIT(1); else CP_WAIT(0);
        __syncthreads();
        int s = i & 1;
        const uint32_t* As32 = (const uint32_t*)(smc + s * UA_BUF);
        const uint32_t* Bs32 = (const uint32_t*)(smc + 2 * UA_BUF + s * DB_BUF);
#pragma unroll
        for (int s2 = 0; s2 < 2; s2++) {
            int kw = s2 * 8 + t;
            uint32_t a[2][4];
#pragma unroll
            for (int mt = 0; mt < 2; mt++) {
                const uint32_t* ar = As32 + (wm * 32 + mt * 16 + g) * ROWW + kw;
                a[mt][0] = ar[0];
                a[mt][1] = ar[8 * ROWW];
                a[mt][2] = ar[4];
                a[mt][3] = ar[8 * ROWW + 4];
            }
#pragma unroll
            for (int nt = 0; nt < 8; nt++) {
                int n = wn * 64 + nt * 8 + g;
                const uint32_t* bp = Bs32 + n * ROWW + kw;
                uint32_t b0 = bp[0], b1 = bp[4];
                MMA_F16(C[0][nt], a[0], b0, b1);
                MMA_F16(C[1][nt], a[1], b0, b1);
            }
        }
        __syncthreads();
        if (i + 2 < NIT) D_LOAD(i + 2);
    }
#undef D_LOAD

    // epilogue: scale by routing/shared weight, fp16 partial stores
#pragma unroll
    for (int mt = 0; mt < 2; mt++) {
        int m0 = r0 + wm * 32 + mt * 16 + g;
        float w0 = g_weight_list[m0];
        float w1 = g_weight_list[m0 + 8];
#pragma unroll
        for (int nt = 0; nt < 8; nt++) {
            int n = n0 + wn * 64 + nt * 8 + t * 2;
            *reinterpret_cast<__half2*>(g_partialh + (size_t)m0 * DDIM + n) =
                __floats2half2_rn(w0 * C[mt][nt][0], w0 * C[mt][nt][1]);
            *reinterpret_cast<__half2*>(g_partialh + (size_t)(m0 + 8) * DDIM + n) =
                __floats2half2_rn(w1 * C[mt][nt][2], w1 * C[mt][nt][3]);
        }
    }
}

// ---------------- combine: fp16 partials -> f32 out --------------------------
__global__ void __launch_bounds__(256)
k_combine(float* __restrict__ out) {
    int t = blockIdx.x;
    int p0 = g_pos_of[t * TOPK + 0];
    int p1 = g_pos_of[t * TOPK + 1];
    int p2 = g_pos_of[t * TOPK + 2];
    int p3 = g_pos_of[t * TOPK + 3];
    const uint4* a0 = (const uint4*)(g_partialh + (size_t)p0 * DDIM);
    const uint4* a1 = (const uint4*)(g_partialh + (size_t)p1 * DDIM);
    const uint4* a2 = (const uint4*)(g_partialh + (size_t)p2 * DDIM);
    const uint4* a3 = (const uint4*)(g_partialh + (size_t)p3 * DDIM);
    const uint4* as = (const uint4*)(g_partialh + (size_t)(SH0 + t) * DDIM);

    int d = threadIdx.x;                      // 256 threads x 8 halves = 2048
    float2 acc[4];
#pragma unroll
    for (int j = 0; j < 4; j++) { acc[j].x = 0.f; acc[j].y = 0.f; }

    uint4 v;
    const __half2* h;
#define ACC(src)                                                                \
    do {                                                                        \
        v = (src)[d];                                                           \
        h = reinterpret_cast<const __half2*>(&v);                               \
        _Pragma("unroll")                                                       \
        for (int j = 0; j < 4; j++) {                                           \
            float2 f = __half22float2(h[j]);                                    \
            acc[j].x += f.x; acc[j].y += f.y;                                   \
        }                                                                       \
    } while (0)
    ACC(a0); ACC(a1); ACC(a2); ACC(a3); ACC(as);
#undef ACC

    float4 o0, o1;
    o0.x = acc[0].x; o0.y = acc[0].y; o0.z = acc[1].x; o0.w = acc[1].y;
    o1.x = acc[2].x; o1.y = acc[2].y; o1.z = acc[3].x; o1.w = acc[3].y;
    float4* op = (float4*)(out + (size_t)t * DDIM + d * 8);
    op[0] = o0;
    op[1] = o1;
}

// ---------------- launch ------------------------------------------------------
extern "C" void kernel_launch(void* const* d_in, const int* in_sizes, int n_in,
                              void* d_out, int out_size) {
    const float* x   = (const float*)d_in[0];
    const float* gw  = (const float*)d_in[1];
    const float* Wg  = (const float*)d_in[2];
    const float* Wu  = (const float*)d_in[3];
    const float* Wd  = (const float*)d_in[4];
    const float* sWg = (const float*)d_in[5];
    const float* sWu = (const float*)d_in[6];
    const float* sWd = (const float*)d_in[7];
    const float* sgw = (const float*)d_in[8];
    float* out = (float*)d_out;
    (void)in_sizes; (void)n_in; (void)out_size;

    __half *xh, *wgt, *wut, *wdt, *swgt, *swut, *swdt;
    cudaGetSymbolAddress((void**)&xh,   g_Xh);
    cudaGetSymbolAddress((void**)&wgt,  g_Wgt);
    cudaGetSymbolAddress((void**)&wut,  g_Wut);
    cudaGetSymbolAddress((void**)&wdt,  g_Wdt);
    cudaGetSymbolAddress((void**)&swgt, g_sWgt);
    cudaGetSymbolAddress((void**)&swut, g_sWut);
    cudaGetSymbolAddress((void**)&swdt, g_sWdt);

    // X: flat f32 -> fp16
    const int XN4 = TNUM * DDIM / 4;
    k_cvth<<<(XN4 + 255) / 256, 256>>>((const float4*)x, (uint2*)xh, XN4);
    // Weights: 64x64 transpose + fp16 round. Wg/Wu [D][F] -> [F][D]; Wd [F][D] -> [D][F]
    k_trh64<<<dim3(FDIM / 64, DDIM / 64, ENUM), 256>>>(Wg,  wgt,  DDIM, FDIM);
    k_trh64<<<dim3(FDIM / 64, DDIM / 64, ENUM), 256>>>(Wu,  wut,  DDIM, FDIM);
    k_trh64<<<dim3(DDIM / 64, FDIM / 64, ENUM), 256>>>(Wd,  wdt,  FDIM, DDIM);
    k_trh64<<<dim3(FDIM / 64, DDIM / 64, 1),    256>>>(sWg, swgt, DDIM, FDIM);
    k_trh64<<<dim3(FDIM / 64, DDIM / 64, 1),    256>>>(sWu, swut, DDIM, FDIM);
    k_trh64<<<dim3(DDIM / 64, FDIM / 64, 1),    256>>>(sWd, swdt, FDIM, DDIM);

    k_init<<<8, 256>>>();
    k_router<<<TNUM, 128>>>(x, gw, sgw);
    k_scan<<<1, 1>>>();
    k_scatter<<<(TNUM * TOPK + 255) / 256, 256>>>();

    k_upgate<<<dim3(MAXT, FDIM / 64), 256, U_SMEM>>>();
    k_down<<<dim3(MAXT, DDIM / 128), 256, D_SMEM>>>();
    k_combine<<<TNUM, 256>>>(out);
}

// round 15
// speedup vs baseline: 2.1100x; 1.0673x over previous
#include <cuda_runtime.h>
#include <cuda_fp16.h>
#include <math.h>
#include <stdint.h>

#define TNUM 2048
#define DDIM 2048
#define FDIM 512
#define ENUM 16
#define TOPK 4
#define MT   128
#define SH0  (TNUM * TOPK + ENUM * MT)   // 10240
#define HROWS (SH0 + TNUM)               // 12288
#define MAXT (HROWS / MT)                // 96

// ---------------- device scratch -------------------------------------------
__device__ float g_comb_w[TNUM * TOPK];
__device__ int   g_topk[TNUM * TOPK];
__device__ int   g_counts[ENUM];
__device__ int   g_offsets[ENUM + 1];
__device__ int   g_cursor[ENUM];
__device__ int   g_token_list[HROWS];
__device__ float g_weight_list[HROWS];
__device__ int   g_pos_of[TNUM * TOPK];
__device__ int   g_tile_seg[MAXT];
__device__ int   g_tile_r0[MAXT];
__device__ int   g_ntiles;
__device__ __half g_partialh[(size_t)HROWS * DDIM];         // fp16 partial rows
// fp16 operands
__device__ __half g_Xh[(size_t)TNUM * DDIM];                // [m][D]
__device__ __half g_Hh[(size_t)HROWS * FDIM];               // [row][F]
__device__ __half g_Wgt[(size_t)ENUM * FDIM * DDIM];        // [F][D] K-major
__device__ __half g_Wut[(size_t)ENUM * FDIM * DDIM];
__device__ __half g_Wdt[(size_t)ENUM * DDIM * FDIM];        // [D][F] K-major
__device__ __half g_sWgt[(size_t)FDIM * DDIM];
__device__ __half g_sWut[(size_t)FDIM * DDIM];
__device__ __half g_sWdt[(size_t)DDIM * FDIM];

// ---------------- helpers ----------------------------------------------------
__device__ __forceinline__ uint32_t smem_u32(const void* p) {
    uint32_t a;
    asm("{ .reg .u64 t; cvta.to.shared.u64 t, %1; cvt.u32.u64 %0, t; }" : "=r"(a) : "l"(p));
    return a;
}
__device__ __forceinline__ void cpa16(uint32_t dst, const void* src, bool valid) {
    int sz = valid ? 16 : 0;
    asm volatile("cp.async.cg.shared.global [%0], [%1], 16, %2;"
                 :: "r"(dst), "l"(src), "r"(sz) : "memory");
}
#define CP_COMMIT() asm volatile("cp.async.commit_group;" ::: "memory")
#define CP_WAIT(n)  asm volatile("cp.async.wait_group %0;" :: "n"(n) : "memory")

// m16n8k16 fp16 -> f32 accumulate
#define MMA_F16(C, A, b0, b1)                                                   \
    asm volatile("mma.sync.aligned.m16n8k16.row.col.f32.f16.f16.f32 "           \
                 "{%0,%1,%2,%3}, {%4,%5,%6,%7}, {%8,%9}, {%0,%1,%2,%3};"        \
                 : "+f"((C)[0]), "+f"((C)[1]), "+f"((C)[2]), "+f"((C)[3])       \
                 : "r"((A)[0]), "r"((A)[1]), "r"((A)[2]), "r"((A)[3]),          \
                   "r"(b0), "r"(b1))

__device__ __forceinline__ float silu_mul(float g, float u) {
    return g / (1.f + expf(-g)) * u;
}

// ---------------- transpose tile body (XOR-swizzled, 64x64) ------------------
__device__ __forceinline__ void tr_tile(const float* __restrict__ src,
                                        __half* __restrict__ dst,
                                        int R, int C, int cb, int rb) {
    __shared__ float sm[64 * 64];
    int c0 = cb * 64, r0 = rb * 64;
    int tid = threadIdx.x;
    int lr = tid >> 4, lc4 = tid & 15;
    int perm_s = (2 * lc4) & 31;
#pragma unroll
    for (int p = 0; p < 4; p++) {
        int r = lr + p * 16;
        float4 v = *reinterpret_cast<const float4*>(&src[(size_t)(r0 + r) * C + c0 + lc4 * 4]);
        int rs = r ^ perm_s;
        sm[(lc4 * 4 + 0) * 64 + rs] = v.x;
        sm[(lc4 * 4 + 1) * 64 + rs] = v.y;
        sm[(lc4 * 4 + 2) * 64 + rs] = v.z;
        sm[(lc4 * 4 + 3) * 64 + rs] = v.w;
    }
    __syncthreads();
    int sc = tid >> 5, sr2 = tid & 31;
#pragma unroll
    for (int p = 0; p < 8; p++) {
        int c = sc + p * 8;
        int perm = (2 * (c >> 2)) & 31;
        float2 v = *reinterpret_cast<const float2*>(&sm[c * 64 + ((sr2 * 2) ^ perm)]);
        __half2 h = __floats2half2_rn(v.x, v.y);
        *reinterpret_cast<__half2*>(&dst[(size_t)(c0 + c) * R + r0 + sr2 * 2]) = h;
    }
}

// ---------------- prep A: Wg/Wu/sWg/sWu transposes + dispatch init -----------
// grid (8, 32, 34): z<16 Wg[z]; z==16 sWg (+init); 17<=z<33 Wu[z-17]; z==33 sWu
__global__ void __launch_bounds__(256)
k_prep_gu(const float* __restrict__ Wg, const float* __restrict__ Wu,
          const float* __restrict__ sWg, const float* __restrict__ sWu) {
    __half *wgt, *wut, *swgt, *swut;
    asm("cvta.global.u64 %0, g_Wgt;"  : "=l"(wgt));
    asm("cvta.global.u64 %0, g_Wut;"  : "=l"(wut));
    asm("cvta.global.u64 %0, g_sWgt;" : "=l"(swgt));
    asm("cvta.global.u64 %0, g_sWut;" : "=l"(swut));

    int z = blockIdx.z;
    const float* src;
    __half* dst;
    if (z < 16)       { src = Wg + (size_t)z * DDIM * FDIM;        dst = wgt + (size_t)z * DDIM * FDIM; }
    else if (z == 16) { src = sWg;                                  dst = swgt; }
    else if (z < 33)  { src = Wu + (size_t)(z - 17) * DDIM * FDIM; dst = wut + (size_t)(z - 17) * DDIM * FDIM; }
    else              { src = sWu;                                  dst = swut; }

    if (z == 16) {   // init duty: 256 blocks x 256 threads
        int id = (blockIdx.y * gridDim.x + blockIdx.x) * blockDim.x + threadIdx.x;
        if (id < ENUM) g_counts[id] = 0;
        if (id < SH0) g_token_list[id] = -1;               // 65536 >= SH0
        if (id < TNUM) g_token_list[SH0 + id] = id;
    }
    tr_tile(src, dst, DDIM, FDIM, blockIdx.x, blockIdx.y);
}

// ---------------- prep B: Wd/sWd transposes ----------------------------------
// grid (32, 8, 17): z<16 Wd[z]; z==16 sWd
__global__ void __launch_bounds__(256)
k_prep_d(const float* __restrict__ Wd, const float* __restrict__ sWd) {
    __half *wdt, *swdt;
    asm("cvta.global.u64 %0, g_Wdt;"  : "=l"(wdt));
    asm("cvta.global.u64 %0, g_sWdt;" : "=l"(swdt));
    int z = blockIdx.z;
    const float* src = (z < 16) ? Wd + (size_t)z * FDIM * DDIM : sWd;
    __half* dst      = (z < 16) ? wdt + (size_t)z * FDIM * DDIM : swdt;
    tr_tile(src, dst, FDIM, DDIM, blockIdx.x, blockIdx.y);
}

// ---------------- router (+ X f32->fp16 conversion fused) --------------------
__global__ void k_router(const float* __restrict__ x,
                         const float* __restrict__ gate_w,
                         const float* __restrict__ sgw) {
    int t = blockIdx.x;
    const float* xr = x + (size_t)t * DDIM;
    __half* xh = g_Xh + (size_t)t * DDIM;
    float acc[17];
#pragma unroll
    for (int e = 0; e < 17; e++) acc[e] = 0.f;
    for (int d = threadIdx.x; d < DDIM; d += blockDim.x) {
        float xv = xr[d];
        xh[d] = __float2half_rn(xv);          // fused conversion
#pragma unroll
        for (int e = 0; e < ENUM; e++) acc[e] += xv * gate_w[e * DDIM + d];
        acc[16] += xv * sgw[d];
    }
#pragma unroll
    for (int off = 16; off; off >>= 1)
#pragma unroll
        for (int e = 0; e < 17; e++) acc[e] += __shfl_down_sync(0xffffffffu, acc[e], off);
    __shared__ float red[17][4];
    int warp = threadIdx.x >> 5, lane = threadIdx.x & 31;
    if (lane == 0)
#pragma unroll
        for (int e = 0; e < 17; e++) red[e][warp] = acc[e];
    __syncthreads();
    if (threadIdx.x == 0) {
        float v[17];
#pragma unroll
        for (int e = 0; e < 17; e++) v[e] = red[e][0] + red[e][1] + red[e][2] + red[e][3];
        float lv[16];
#pragma unroll
        for (int e = 0; e < ENUM; e++) lv[e] = v[e];
        int idx[TOPK]; float lg[TOPK];
#pragma unroll
        for (int k = 0; k < TOPK; k++) {
            int bi = 0; float bv = lv[0];
#pragma unroll
            for (int e = 1; e < ENUM; e++) if (lv[e] > bv) { bv = lv[e]; bi = e; }
            idx[k] = bi; lg[k] = bv; lv[bi] = -1e30f;
        }
        float mx = lg[0], s = 0.f, w[TOPK];
#pragma unroll
        for (int k = 0; k < TOPK; k++) { w[k] = expf(lg[k] - mx); s += w[k]; }
        float inv = 1.f / s;
#pragma unroll
        for (int k = 0; k < TOPK; k++) {
            g_topk[t * TOPK + k]   = idx[k];
            g_comb_w[t * TOPK + k] = w[k] * inv;
            atomicAdd(&g_counts[idx[k]], 1);
        }
        g_weight_list[SH0 + t] = 1.f / (1.f + expf(-v[16]));
    }
}

__global__ void k_scan() {
    if (threadIdx.x == 0 && blockIdx.x == 0) {
        int o = 0, nt = 0;
        for (int e = 0; e < ENUM; e++) {
            g_offsets[e] = o;
            g_cursor[e]  = o;
            int c = (g_counts[e] + MT - 1) & ~(MT - 1);
            for (int r = 0; r < c; r += MT) { g_tile_seg[nt] = e; g_tile_r0[nt] = o + r; nt++; }
            o += c;
        }
        g_offsets[ENUM] = o;
        for (int r = 0; r < TNUM; r += MT) { g_tile_seg[nt] = ENUM; g_tile_r0[nt] = SH0 + r; nt++; }
        g_ntiles = nt;
    }
}

__global__ void k_scatter() {
    int i = blockIdx.x * blockDim.x + threadIdx.x;
    if (i < TNUM * TOPK) {
        int e = g_topk[i];
        int pos = atomicAdd(&g_cursor[e], 1);
        g_token_list[pos]  = i / TOPK;
        g_weight_list[pos] = g_comb_w[i];
        g_pos_of[i]        = pos;
    }
}

// ---------------- SMEM geometry ----------------------------------------------
#define ROWB   80
#define ROWW   20
#define UA_BUF (128 * ROWB)                 // 10240 B
#define UB_BUF (64 * ROWB)                  // 5120 B
#define U_SMEM (2 * UA_BUF + 4 * UB_BUF)    // 40960 B
#define DB_BUF (128 * ROWB)                 // 10240 B
#define D_SMEM (2 * UA_BUF + 2 * DB_BUF)    // 40960 B

// ---------------- upgate: H = silu(X@Wg) * (X@Wu)  (fp16 m16n8k16) -----------
__global__ void __launch_bounds__(256, 2)
k_upgate() {
    int ti = blockIdx.x;
    if (ti >= g_ntiles) return;
    int z  = g_tile_seg[ti];
    int r0 = g_tile_r0[ti];
    int f0 = blockIdx.y * 64;

    const __half* Wg = (z == ENUM) ? g_sWgt : g_Wgt + (size_t)z * FDIM * DDIM;
    const __half* Wu = (z == ENUM) ? g_sWut : g_Wut + (size_t)z * FDIM * DDIM;

    extern __shared__ char smc[];
    uint32_t smb = smem_u32(smc);
    __shared__ int s_tok[MT];

    int tid = threadIdx.x, lane = tid & 31;
    int warp = tid >> 5, wm = warp & 3, wf = warp >> 2;
    int g = lane >> 2, t = lane & 3;

    if (tid < MT) s_tok[tid] = g_token_list[r0 + tid];
    __syncthreads();

    float Cg[2][4][4], Cu[2][4][4];
#pragma unroll
    for (int mt = 0; mt < 2; mt++)
#pragma unroll
        for (int nt = 0; nt < 4; nt++)
#pragma unroll
            for (int q = 0; q < 4; q++) { Cg[mt][nt][q] = 0.f; Cu[mt][nt][q] = 0.f; }

#define U_LOAD(i)                                                               \
    do {                                                                        \
        int s_ = (i) & 1;                                                       \
        uint32_t a_  = smb + s_ * UA_BUF;                                       \
        uint32_t bg_ = smb + 2 * UA_BUF + s_ * UB_BUF;                          \
        uint32_t bu_ = smb + 2 * UA_BUF + 2 * UB_BUF + s_ * UB_BUF;             \
        _Pragma("unroll")                                                       \
        for (int p = 0; p < 2; p++) {                                           \
            int idx = tid + p * 256;                                            \
            int row = idx >> 2, ch = idx & 3;                                   \
            int tok = s_tok[row];                                               \
            cpa16(a_ + row * ROWB + ch * 16,                                    \
                  g_Xh + (size_t)(tok < 0 ? 0 : tok) * DDIM + (i) * 32 + ch * 8,\
                  tok >= 0);                                                    \
        }                                                                       \
        {                                                                       \
            int row = tid >> 2, ch = tid & 3;                                   \
            cpa16(bg_ + row * ROWB + ch * 16,                                   \
                  Wg + (size_t)(f0 + row) * DDIM + (i) * 32 + ch * 8, true);    \
            cpa16(bu_ + row * ROWB + ch * 16,                                   \
                  Wu + (size_t)(f0 + row) * DDIM + (i) * 32 + ch * 8, true);    \
        }                                                                       \
        CP_COMMIT();                                                            \
    } while (0)

    const int NIT = DDIM / 32;   // 64
    U_LOAD(0);
    U_LOAD(1);
    for (int i = 0; i < NIT; i++) {
        if (i + 1 < NIT) CP_WAIT(1); else CP_WAIT(0);
        __syncthreads();
        int s = i & 1;
        const uint32_t* As32 = (const uint32_t*)(smc + s * UA_BUF);
        const uint32_t* Bg32 = (const uint32_t*)(smc + 2 * UA_BUF + s * UB_BUF);
        const uint32_t* Bu32 = (const uint32_t*)(smc + 2 * UA_BUF + 2 * UB_BUF + s * UB_BUF);
#pragma unroll
        for (int s2 = 0; s2 < 2; s2++) {
            int kw = s2 * 8 + t;
            uint32_t a[2][4];
#pragma unroll
            for (int mt = 0; mt < 2; mt++) {
                const uint32_t* ar = As32 + (wm * 32 + mt * 16 + g) * ROWW + kw;
                a[mt][0] = ar[0];
                a[mt][1] = ar[8 * ROWW];
                a[mt][2] = ar[4];
                a[mt][3] = ar[8 * ROWW + 4];
            }
#pragma unroll
            for (int nt = 0; nt < 4; nt++) {
                int n = wf * 32 + nt * 8 + g;
                const uint32_t* bp = Bg32 + n * ROWW + kw;
                uint32_t b0 = bp[0], b1 = bp[4];
                MMA_F16(Cg[0][nt], a[0], b0, b1);
                MMA_F16(Cg[1][nt], a[1], b0, b1);
                bp = Bu32 + n * ROWW + kw;
                b0 = bp[0]; b1 = bp[4];
                MMA_F16(Cu[0][nt], a[0], b0, b1);
                MMA_F16(Cu[1][nt], a[1], b0, b1);
            }
        }
        __syncthreads();
        if (i + 2 < NIT) U_LOAD(i + 2);
    }
#undef U_LOAD

#pragma unroll
    for (int mt = 0; mt < 2; mt++) {
        int m0 = r0 + wm * 32 + mt * 16 + g;
#pragma unroll
        for (int nt = 0; nt < 4; nt++) {
            int fb = f0 + wf * 32 + nt * 8 + 2 * t;
            __half2 h;
            h = __floats2half2_rn(silu_mul(Cg[mt][nt][0], Cu[mt][nt][0]),
                                  silu_mul(Cg[mt][nt][1], Cu[mt][nt][1]));
            *reinterpret_cast<__half2*>(g_Hh + (size_t)m0 * FDIM + fb) = h;
            h = __floats2half2_rn(silu_mul(Cg[mt][nt][2], Cu[mt][nt][2]),
                                  silu_mul(Cg[mt][nt][3], Cu[mt][nt][3]));
            *reinterpret_cast<__half2*>(g_Hh + (size_t)(m0 + 8) * FDIM + fb) = h;
        }
    }
}

// ---------------- down: partial = w * (H @ Wd)  (fp16 m16n8k16) --------------
__global__ void __launch_bounds__(256, 2)
k_down() {
    int ti = blockIdx.x;
    if (ti >= g_ntiles) return;
    int z  = g_tile_seg[ti];
    int r0 = g_tile_r0[ti];
    int n0 = blockIdx.y * 128;

    const __half* Wd = (z == ENUM) ? g_sWdt : g_Wdt + (size_t)z * DDIM * FDIM;

    extern __shared__ char smc[];
    uint32_t smb = smem_u32(smc);

    int tid = threadIdx.x, lane = tid & 31;
    int warp = tid >> 5, wm = warp & 3, wn = warp >> 2;
    int g = lane >> 2, t = lane & 3;

    float C[2][8][4];
#pragma unroll
    for (int mt = 0; mt < 2; mt++)
#pragma unroll
        for (int nt = 0; nt < 8; nt++)
#pragma unroll
            for (int q = 0; q < 4; q++) C[mt][nt][q] = 0.f;

#define D_LOAD(i)                                                               \
    do {                                                                        \
        int s_ = (i) & 1;                                                       \
        uint32_t a_ = smb + s_ * UA_BUF;                                        \
        uint32_t b_ = smb + 2 * UA_BUF + s_ * DB_BUF;                           \
        _Pragma("unroll")                                                       \
        for (int p = 0; p < 2; p++) {                                           \
            int idx = tid + p * 256;                                            \
            int row = idx >> 2, ch = idx & 3;                                   \
            cpa16(a_ + row * ROWB + ch * 16,                                    \
                  g_Hh + (size_t)(r0 + row) * FDIM + (i) * 32 + ch * 8, true);  \
            cpa16(b_ + row * ROWB + ch * 16,                                    \
                  Wd + (size_t)(n0 + row) * FDIM + (i) * 32 + ch * 8, true);    \
        }                                                                       \
        CP_COMMIT();                                                            \
    } while (0)

    const int NIT = FDIM / 32;   // 16
    D_LOAD(0);
    D_LOAD(1);
    for (int i = 0; i < NIT; i++) {
        if (i + 1 < NIT) CP_WAIT(1); else CP_WAIT(0);
        __syncthreads();
        int s = i & 1;
        const uint32_t* As32 = (const uint32_t*)(smc + s * UA_BUF);
        const uint32_t* Bs32 = (const uint32_t*)(smc + 2 * UA_BUF + s * DB_BUF);
#pragma unroll
        for (int s2 = 0; s2 < 2; s2++) {
            int kw = s2 * 8 + t;
            uint32_t a[2][4];
#pragma unroll
            for (int mt = 0; mt < 2; mt++) {
                const uint32_t* ar = As32 + (wm * 32 + mt * 16 + g) * ROWW + kw;
                a[mt][0] = ar[0];
                a[mt][1] = ar[8 * ROWW];
                a[mt][2] = ar[4];
                a[mt][3] = ar[8 * ROWW + 4];
            }
#pragma unroll
            for (int nt = 0; nt < 8; nt++) {
                int n = wn * 64 + nt * 8 + g;
                const uint32_t* bp = Bs32 + n * ROWW + kw;
                uint32_t b0 = bp[0], b1 = bp[4];
                MMA_F16(C[0][nt], a[0], b0, b1);
                MMA_F16(C[1][nt], a[1], b0, b1);
            }
        }
        __syncthreads();
        if (i + 2 < NIT) D_LOAD(i + 2);
    }
#undef D_LOAD

#pragma unroll
    for (int mt = 0; mt < 2; mt++) {
        int m0 = r0 + wm * 32 + mt * 16 + g;
        float w0 = g_weight_list[m0];
        float w1 = g_weight_list[m0 + 8];
#pragma unroll
        for (int nt = 0; nt < 8; nt++) {
            int n = n0 + wn * 64 + nt * 8 + t * 2;
            *reinterpret_cast<__half2*>(g_partialh + (size_t)m0 * DDIM + n) =
                __floats2half2_rn(w0 * C[mt][nt][0], w0 * C[mt][nt][1]);
            *reinterpret_cast<__half2*>(g_partialh + (size_t)(m0 + 8) * DDIM + n) =
                __floats2half2_rn(w1 * C[mt][nt][2], w1 * C[mt][nt][3]);
        }
    }
}

// ---------------- combine: fp16 partials -> f32 out --------------------------
__global__ void __launch_bounds__(256)
k_combine(float* __restrict__ out) {
    int t = blockIdx.x;
    int p0 = g_pos_of[t * TOPK + 0];
    int p1 = g_pos_of[t * TOPK + 1];
    int p2 = g_pos_of[t * TOPK + 2];
    int p3 = g_pos_of[t * TOPK + 3];
    const uint4* a0 = (const uint4*)(g_partialh + (size_t)p0 * DDIM);
    const uint4* a1 = (const uint4*)(g_partialh + (size_t)p1 * DDIM);
    const uint4* a2 = (const uint4*)(g_partialh + (size_t)p2 * DDIM);
    const uint4* a3 = (const uint4*)(g_partialh + (size_t)p3 * DDIM);
    const uint4* as = (const uint4*)(g_partialh + (size_t)(SH0 + t) * DDIM);

    int d = threadIdx.x;
    float2 acc[4];
#pragma unroll
    for (int j = 0; j < 4; j++) { acc[j].x = 0.f; acc[j].y = 0.f; }

    uint4 v;
    const __half2* h;
#define ACC(src)                                                                \
    do {                                                                        \
        v = (src)[d];                                                           \
        h = reinterpret_cast<const __half2*>(&v);                               \
        _Pragma("unroll")                                                       \
        for (int j = 0; j < 4; j++) {                                           \
            float2 f = __half22float2(h[j]);                                    \
            acc[j].x += f.x; acc[j].y += f.y;                                   \
        }                                                                       \
    } while (0)
    ACC(a0); ACC(a1); ACC(a2); ACC(a3); ACC(as);
#undef ACC

    float4 o0, o1;
    o0.x = acc[0].x; o0.y = acc[0].y; o0.z = acc[1].x; o0.w = acc[1].y;
    o1.x = acc[2].x; o1.y = acc[2].y; o1.z = acc[3].x; o1.w = acc[3].y;
    float4* op = (float4*)(out + (size_t)t * DDIM + d * 8);
    op[0] = o0;
    op[1] = o1;
}

// ---------------- launch ------------------------------------------------------
extern "C" void kernel_launch(void* const* d_in, const int* in_sizes, int n_in,
                              void* d_out, int out_size) {
    const float* x   = (const float*)d_in[0];
    const float* gw  = (const float*)d_in[1];
    const float* Wg  = (const float*)d_in[2];
    const float* Wu  = (const float*)d_in[3];
    const float* Wd  = (const float*)d_in[4];
    const float* sWg = (const float*)d_in[5];
    const float* sWu = (const float*)d_in[6];
    const float* sWd = (const float*)d_in[7];
    const float* sgw = (const float*)d_in[8];
    float* out = (float*)d_out;
    (void)in_sizes; (void)n_in; (void)out_size;

    // launch index 5 = k_upgate (ncu -s 5 -c 1 samples it)
    k_prep_gu<<<dim3(FDIM / 64, DDIM / 64, 34), 256>>>(Wg, Wu, sWg, sWu);   // 0
    k_prep_d <<<dim3(DDIM / 64, FDIM / 64, 17), 256>>>(Wd, sWd);            // 1
    k_router <<<TNUM, 128>>>(x, gw, sgw);                                    // 2
    k_scan   <<<1, 1>>>();                                                   // 3
    k_scatter<<<(TNUM * TOPK + 255) / 256, 256>>>();                         // 4
    k_upgate <<<dim3(MAXT, FDIM / 64), 256, U_SMEM>>>();                     // 5
    k_down   <<<dim3(MAXT, DDIM / 128), 256, D_SMEM>>>();                    // 6
    k_combine<<<TNUM, 256>>>(out);                                           // 7
}